// round 6
// baseline (speedup 1.0000x reference)
#include <cuda_runtime.h>
#include <cstdint>

// Problem constants
#define LNUM 2
#define BB   128
#define CIN  64
#define EE   64
#define NHH  8
#define MEM  40
#define HD   8
#define THD  512         // HD*HW
#define PIX  64          // spatial size
#define C_MAIN 192       // CIN + 2E
#define C_PROJ 128       // CIN + E
#define CO_MAIN 320      // 5E
#define CO_PROJ 192      // 3E

#define CHW   120        // padded channel stride in smem (10 rows x 12 cols)
#define SIN_F 7680       // 64 channels * CHW
#define WSTR2 148        // per-co duplicated-weight stride (floats); 148 mod 32 = 20
#define WT2_F (64 * WSTR2)
#define CONV_SMEM ((SIN_F + WT2_F) * 4)   // 68608 B

typedef unsigned long long u64;

// ---------------- scratch (device globals; no allocation) ----------------
__device__ float g_inp  [BB * C_MAIN * PIX];   // (B,192,64)
__device__ float g_gates[BB * CO_MAIN * PIX];  // (B,320,64)
__device__ float g_kqv  [BB * CO_PROJ * PIX];  // (B,192,64)
__device__ float g_attn [BB * EE * PIX];       // (B,64,64)
__device__ float g_out  [BB * EE * PIX];       // (B,64,64)
__device__ float g_bias [BB * MEM];
__device__ float g_nd   [BB];
__device__ int   g_is_i32;

__device__ __forceinline__ float sigmoidf_(float v) {
    return 1.0f / (1.0f + __expf(-v));
}

// ---------------- packed f32x2 helpers (sm_103a) ----------------
__device__ __forceinline__ u64 fma2(u64 a, u64 b, u64 c) {
    u64 d;
    asm("fma.rn.f32x2 %0, %1, %2, %3;" : "=l"(d) : "l"(a), "l"(b), "l"(c));
    return d;
}
__device__ __forceinline__ u64 pk(float lo, float hi) {
    u64 r;
    asm("mov.b64 %0, {%1, %2};" : "=l"(r) : "f"(lo), "f"(hi));
    return r;
}
__device__ __forceinline__ float2 unpk(u64 v) {
    float2 r;
    asm("mov.b64 {%0, %1}, %2;" : "=f"(r.x), "=f"(r.y) : "l"(v));
    return r;
}

// ---------------- dtype detection for bool inputs (parallel) ----------------
__global__ void detect_kernel(const int* __restrict__ sm) {
    __shared__ int bad;
    if (threadIdx.x == 0) bad = 0;
    __syncthreads();
    int anybad = 0;
    for (int i = threadIdx.x; i < (BB * MEM) / 4; i += 256) {
        int v = sm[i];
        if (v != 0 && v != 1) anybad = 1;
    }
    if (anybad) bad = 1;
    __syncthreads();
    if (threadIdx.x == 0) g_is_i32 = !bad;
}

__device__ __forceinline__ int read_bool(const void* p, int idx) {
    if (g_is_i32) return ((const int*)p)[idx] != 0;
    return ((const unsigned char*)p)[idx] != 0;
}

// ---------------- bias + notdone ----------------
__global__ void bias_kernel(const void* __restrict__ src_mask,
                            const void* __restrict__ notdone) {
    int t = blockIdx.x * 256 + threadIdx.x;
    if (t < BB) g_nd[t] = read_bool(notdone, t) ? 1.0f : 0.0f;
    if (t >= BB * MEM) return;
    int b = t / MEM, m = t - b * MEM;
    float v;
    if (m == MEM - 1) {
        v = 3.0f;  // MASK_B
    } else {
        bool masked = read_bool(src_mask, b * MEM + m + 1) || !read_bool(notdone, b);
        v = masked ? -1e9f : 0.0f;
    }
    g_bias[t] = v;
}

// ---------------- build concat input (x | out | h*nd) ----------------
__global__ void prep_kernel(const float* __restrict__ x,
                            const float* __restrict__ h0,
                            int n, int first) {
    int idx = blockIdx.x * 256 + threadIdx.x;
    if (idx >= BB * C_MAIN * PIX) return;
    int b = idx / (C_MAIN * PIX);
    int r = idx - b * (C_MAIN * PIX);
    int c = r >> 6;
    int p = r & 63;
    float nd = g_nd[b];
    float v;
    if (c < CIN) {
        v = x[b * (CIN * PIX) + r];
    } else if (c < CIN + EE) {
        int off = b * (EE * PIX) + (c - CIN) * PIX + p;
        if (first)
            v = h0[((size_t)(LNUM - 1) * BB + b) * (EE * PIX) + (c - CIN) * PIX + p] * nd;
        else
            v = g_out[off];
    } else {
        v = h0[((size_t)n * BB + b) * (EE * PIX) + (c - CIN - EE) * PIX + p] * nd;
    }
    g_inp[idx] = v;
}

// ---------------- fused main(192->320) + proj(128->192) 3x3 SAME conv ----
// grid = (B, 8): y<5 -> main co [64y,...), y>=5 -> proj co [64(y-5),...)
// 256 threads: thread (row = tid&7, cog = tid>>3) computes co = cobase+cog
// and co = cobase+cog+32 over 8 pixels (4 f32x2 pairs) of its row.
// Inner loop uses packed fma.rn.f32x2: 72 FFMA2 per cc instead of 144 FFMA.
// Weights staged DUPLICATED (w,w) in smem, read as conflict-free LDS.64.
__global__ void __launch_bounds__(256, 2)
conv_fused_kernel(const float* __restrict__ main_w,
                  const float* __restrict__ main_b,
                  const float* __restrict__ proj_w,
                  const float* __restrict__ proj_b,
                  int n) {
    extern __shared__ float smem[];
    float* sin = smem;          // SIN_F: 64ch x (10 rows x 12 cols)
    float* wt  = smem + SIN_F;  // WT2_F: 64co x WSTR2 (8 cc x 9 dup pairs)

    int b = blockIdx.x;
    int y = blockIdx.y;
    bool ismain = (y < 5);
    int cobase = ismain ? y * 64 : (y - 5) * 64;
    int cin    = ismain ? C_MAIN : C_PROJ;
    int nchunk = cin >> 6;
    const float* wsrc = ismain
        ? main_w + (size_t)n * CO_MAIN * C_MAIN * 9
        : proj_w + (size_t)n * CO_PROJ * C_PROJ * 9;
    const float* inp = g_inp + (size_t)b * C_MAIN * PIX;

    int tid = threadIdx.x;
    int row = tid & 7;
    int cog = tid >> 3;       // 0..31
    int co_s = tid >> 2;      // staging: 4 threads per co
    int part = tid & 3;       // covers cc = 2*part, 2*part+1

    u64 acc0v[4], acc1v[4];
#pragma unroll
    for (int j = 0; j < 4; j++) { acc0v[j] = 0ull; acc1v[j] = 0ull; }

    // zero input smem once (padding stays 0; interior overwritten per chunk)
    for (int i = tid; i < SIN_F; i += 256) sin[i] = 0.0f;

    for (int chunk = 0; chunk < nchunk; chunk++) {
        int c0 = chunk * 64;
        __syncthreads();   // previous compute done before refill
        for (int i = tid; i < 64 * PIX; i += 256) {
            int ch = i >> 6, p = i & 63;
            sin[ch * CHW + ((p >> 3) + 1) * 12 + (p & 7) + 1] = inp[(c0 + ch) * PIX + p];
        }
        for (int cs = 0; cs < 64; cs += 8) {
            __syncthreads();   // prior compute done / input ready
            {
                // stage 2 cc x 9 weights per thread, duplicated (w,w)
                const float* src = wsrc + (size_t)(cobase + co_s) * cin * 9
                                        + (c0 + cs + 2 * part) * 9;
                float* dst = wt + co_s * WSTR2 + (2 * part) * 18;
#pragma unroll
                for (int k = 0; k < 9; k++) {
                    float w = src[k];
                    dst[2 * k] = w; dst[2 * k + 1] = w;
                }
#pragma unroll
                for (int k = 0; k < 9; k++) {
                    float w = src[9 + k];
                    dst[18 + 2 * k] = w; dst[18 + 2 * k + 1] = w;
                }
            }
            __syncthreads();
#pragma unroll
            for (int cc = 0; cc < 8; cc++) {
                const float* s = sin + (cs + cc) * CHW + row * 12;
                const u64* W0 = (const u64*)(wt + cog * WSTR2 + cc * 18);
                const u64* W1 = (const u64*)(wt + (cog + 32) * WSTR2 + cc * 18);
#pragma unroll
                for (int r = 0; r < 3; r++) {
                    float4 fa = *(const float4*)(s + r * 12 + 0);
                    float4 fb = *(const float4*)(s + r * 12 + 4);
                    float4 fc = *(const float4*)(s + r * 12 + 8);
                    u64 ev0 = pk(fa.x, fa.y);
                    u64 ev1 = pk(fa.z, fa.w);
                    u64 ev2 = pk(fb.x, fb.y);
                    u64 ev3 = pk(fb.z, fb.w);
                    u64 ev4 = pk(fc.x, fc.y);
                    u64 od0 = pk(fa.y, fa.z);
                    u64 od1 = pk(fa.w, fb.x);
                    u64 od2 = pk(fb.y, fb.z);
                    u64 od3 = pk(fb.w, fc.x);
                    u64 wa0 = W0[r * 3 + 0], wa1 = W0[r * 3 + 1], wa2 = W0[r * 3 + 2];
                    u64 wb0 = W1[r * 3 + 0], wb1 = W1[r * 3 + 1], wb2 = W1[r * 3 + 2];
                    // kk = 0 : even pairs 0..3
                    acc0v[0] = fma2(ev0, wa0, acc0v[0]);
                    acc0v[1] = fma2(ev1, wa0, acc0v[1]);
                    acc0v[2] = fma2(ev2, wa0, acc0v[2]);
                    acc0v[3] = fma2(ev3, wa0, acc0v[3]);
                    acc1v[0] = fma2(ev0, wb0, acc1v[0]);
                    acc1v[1] = fma2(ev1, wb0, acc1v[1]);
                    acc1v[2] = fma2(ev2, wb0, acc1v[2]);
                    acc1v[3] = fma2(ev3, wb0, acc1v[3]);
                    // kk = 1 : odd pairs 0..3
                    acc0v[0] = fma2(od0, wa1, acc0v[0]);
                    acc0v[1] = fma2(od1, wa1, acc0v[1]);
                    acc0v[2] = fma2(od2, wa1, acc0v[2]);
                    acc0v[3] = fma2(od3, wa1, acc0v[3]);
                    acc1v[0] = fma2(od0, wb1, acc1v[0]);
                    acc1v[1] = fma2(od1, wb1, acc1v[1]);
                    acc1v[2] = fma2(od2, wb1, acc1v[2]);
                    acc1v[3] = fma2(od3, wb1, acc1v[3]);
                    // kk = 2 : even pairs 1..4
                    acc0v[0] = fma2(ev1, wa2, acc0v[0]);
                    acc0v[1] = fma2(ev2, wa2, acc0v[1]);
                    acc0v[2] = fma2(ev3, wa2, acc0v[2]);
                    acc0v[3] = fma2(ev4, wa2, acc0v[3]);
                    acc1v[0] = fma2(ev1, wb2, acc1v[0]);
                    acc1v[1] = fma2(ev2, wb2, acc1v[1]);
                    acc1v[2] = fma2(ev3, wb2, acc1v[2]);
                    acc1v[3] = fma2(ev4, wb2, acc1v[3]);
                }
            }
        }
    }

    int co0 = cobase + cog;
    int co1 = cobase + cog + 32;
    float o8[8];
    if (ismain) {
        float b0 = main_b[n * CO_MAIN + co0];
        float b1 = main_b[n * CO_MAIN + co1];
        float* o0 = g_gates + ((size_t)b * CO_MAIN + co0) * PIX + row * 8;
        float* o1 = g_gates + ((size_t)b * CO_MAIN + co1) * PIX + row * 8;
#pragma unroll
        for (int j = 0; j < 4; j++) {
            float2 u = unpk(acc0v[j]);
            o8[2 * j] = u.x + b0; o8[2 * j + 1] = u.y + b0;
        }
        *(float4*)(o0 + 0) = *(float4*)(o8 + 0);
        *(float4*)(o0 + 4) = *(float4*)(o8 + 4);
#pragma unroll
        for (int j = 0; j < 4; j++) {
            float2 u = unpk(acc1v[j]);
            o8[2 * j] = u.x + b1; o8[2 * j + 1] = u.y + b1;
        }
        *(float4*)(o1 + 0) = *(float4*)(o8 + 0);
        *(float4*)(o1 + 4) = *(float4*)(o8 + 4);
    } else {
        float b0 = proj_b[n * CO_PROJ + co0];
        float b1 = proj_b[n * CO_PROJ + co1];
        float* o0 = g_kqv + ((size_t)b * CO_PROJ + co0) * PIX + row * 8;
        float* o1 = g_kqv + ((size_t)b * CO_PROJ + co1) * PIX + row * 8;
#pragma unroll
        for (int j = 0; j < 4; j++) {
            float2 u = unpk(acc0v[j]);
            o8[2 * j] = u.x + b0; o8[2 * j + 1] = u.y + b0;
        }
        *(float4*)(o0 + 0) = *(float4*)(o8 + 0);
        *(float4*)(o0 + 4) = *(float4*)(o8 + 4);
#pragma unroll
        for (int j = 0; j < 4; j++) {
            float2 u = unpk(acc1v[j]);
            o8[2 * j] = u.x + b1; o8[2 * j + 1] = u.y + b1;
        }
        *(float4*)(o1 + 0) = *(float4*)(o8 + 0);
        *(float4*)(o1 + 4) = *(float4*)(o8 + 4);
    }
}

// ---------------- attention over rolling memory ----------------
__global__ void attn_kernel(const float* __restrict__ k0,
                            const float* __restrict__ v0,
                            const float* __restrict__ pos_w,
                            const float* __restrict__ pos_b,
                            int n) {
    int b = blockIdx.x;
    int h = blockIdx.y;
    int tid = threadIdx.x;
    __shared__ float q[THD], kn[THD], vn[THD];
    __shared__ float sc[MEM], wts[MEM];

    const float* kqv = g_kqv + (size_t)b * CO_PROJ * PIX;
    const float rscale = 0.044194173824159216f;  // 1/sqrt(512)
    for (int d = tid; d < THD; d += 256) {
        int hd = d >> 6, hw = d & 63;
        kn[d] = kqv[(h * 24 + hd) * PIX + hw];
        q[d]  = kqv[(h * 24 + 8 + hd) * PIX + hw] * rscale;
        vn[d] = kqv[(h * 24 + 16 + hd) * PIX + hw];
    }
    __syncthreads();

    const float* kb  = k0 + ((((size_t)n * BB + b) * NHH + h) * MEM) * THD;
    const float* pwb = pos_w + (size_t)n * MEM * (NHH * THD) + h * THD;
    int warp = tid >> 5, lane = tid & 31;
    for (int m = warp; m < MEM; m += 8) {
        const float* kr = (m < MEM - 1) ? (kb + (size_t)(m + 1) * THD) : kn;
        const float* pr = pwb + (size_t)m * (NHH * THD);
        float p = 0.0f;
        for (int d = lane; d < THD; d += 32)
            p = fmaf(q[d], kr[d] + pr[d], p);
#pragma unroll
        for (int o = 16; o; o >>= 1) p += __shfl_xor_sync(0xffffffffu, p, o);
        if (lane == 0)
            sc[m] = p + g_bias[b * MEM + m] + pos_b[(size_t)n * MEM * NHH + m * NHH + h];
    }
    __syncthreads();
    if (tid == 0) {
        float mx = sc[0];
#pragma unroll
        for (int m = 1; m < MEM; m++) mx = fmaxf(mx, sc[m]);
        float s = 0.0f;
#pragma unroll
        for (int m = 0; m < MEM; m++) {
            float e = __expf(sc[m] - mx);
            wts[m] = e;
            s += e;
        }
        float inv = 1.0f / s;
#pragma unroll
        for (int m = 0; m < MEM; m++) wts[m] *= inv;
    }
    __syncthreads();

    const float* vb = v0 + ((((size_t)n * BB + b) * NHH + h) * MEM) * THD;
    for (int d = tid; d < THD; d += 256) {
        float acc = wts[MEM - 1] * vn[d];
        for (int m = 0; m < MEM - 1; m++)
            acc = fmaf(wts[m], vb[(size_t)(m + 1) * THD + d], acc);
        int hd = d >> 6, hw = d & 63;
        g_attn[(size_t)b * (EE * PIX) + (h * 8 + hd) * PIX + hw] = acc;
    }
}

// ---------------- out conv + residual + layernorm + LSTM combine ---------
__global__ void final_kernel(const float* __restrict__ out_w,
                             const float* __restrict__ out_b,
                             const float* __restrict__ ln_w,
                             const float* __restrict__ ln_b,
                             const float* __restrict__ c0,
                             const float* __restrict__ x,
                             int n, float* __restrict__ dst_last, int last) {
    __shared__ float sa[EE * 100];   // padded attn input
    __shared__ float ao[EE * PIX];   // conv+residual result
    __shared__ float red[16];
    __shared__ float s_mu, s_rv;
    int b = blockIdx.x;
    int tid = threadIdx.x;

    for (int i = tid; i < EE * 100; i += 256) sa[i] = 0.0f;
    __syncthreads();
    const float* at = g_attn + (size_t)b * EE * PIX;
    for (int i = tid; i < EE * PIX; i += 256) {
        int c = i >> 6, p = i & 63;
        sa[c * 100 + ((p >> 3) + 1) * 10 + (p & 7) + 1] = at[i];
    }
    __syncthreads();

    const float* wb = out_w + (size_t)n * EE * EE * 9;
    const float* xr = x + (size_t)b * EE * PIX;
    for (int t = tid; t < EE * 8; t += 256) {
        int co = t >> 3;
        int row = t & 7;
        const float* wc = wb + (size_t)co * EE * 9;
        float acc[8];
#pragma unroll
        for (int xx = 0; xx < 8; xx++) acc[xx] = 0.0f;
        for (int c = 0; c < EE; c++) {
            const float* s = sa + c * 100 + row * 10;
            const float* w = wc + c * 9;
            float w0 = w[0], w1 = w[1], w2 = w[2];
            float w3 = w[3], w4 = w[4], w5 = w[5];
            float w6 = w[6], w7 = w[7], w8 = w[8];
#pragma unroll
            for (int xx = 0; xx < 8; xx++) {
                float a = acc[xx];
                a = fmaf(s[xx],      w0, a);
                a = fmaf(s[xx + 1],  w1, a);
                a = fmaf(s[xx + 2],  w2, a);
                a = fmaf(s[10 + xx],     w3, a);
                a = fmaf(s[10 + xx + 1], w4, a);
                a = fmaf(s[10 + xx + 2], w5, a);
                a = fmaf(s[20 + xx],     w6, a);
                a = fmaf(s[20 + xx + 1], w7, a);
                a = fmaf(s[20 + xx + 2], w8, a);
                acc[xx] = a;
            }
        }
        float bb = out_b[n * EE + co];
        int base = co * PIX + row * 8;
#pragma unroll
        for (int xx = 0; xx < 8; xx++)
            ao[base + xx] = acc[xx] + bb + xr[base + xx];
    }
    __syncthreads();

    float s1 = 0.0f, s2 = 0.0f;
    for (int i = tid; i < EE * PIX; i += 256) {
        float v = ao[i];
        s1 += v;
        s2 += v * v;
    }
    int warp = tid >> 5, lane = tid & 31;
#pragma unroll
    for (int o = 16; o; o >>= 1) {
        s1 += __shfl_xor_sync(0xffffffffu, s1, o);
        s2 += __shfl_xor_sync(0xffffffffu, s2, o);
    }
    if (lane == 0) { red[warp] = s1; red[8 + warp] = s2; }
    __syncthreads();
    if (tid == 0) {
        float a = 0.0f, q2 = 0.0f;
#pragma unroll
        for (int w2 = 0; w2 < 8; w2++) { a += red[w2]; q2 += red[8 + w2]; }
        float mu = a * (1.0f / 4096.0f);
        float var = q2 * (1.0f / 4096.0f) - mu * mu;
        s_mu = mu;
        s_rv = rsqrtf(var + 1e-5f);
    }
    __syncthreads();
    float mu = s_mu, rv = s_rv;

    const float* gb = g_gates + (size_t)b * CO_MAIN * PIX;
    const float* cb = c0 + ((size_t)n * BB + b) * (EE * PIX);
    float nd = g_nd[b];
    float* dst = (last ? dst_last : g_out) + (size_t)b * EE * PIX;
    const float* lw = ln_w + (size_t)n * EE * PIX;
    const float* lb = ln_b + (size_t)n * EE * PIX;
    for (int i = tid; i < EE * PIX; i += 256) {
        int c = i >> 6, p = i & 63;
        float aon = (ao[i] - mu) * rv * lw[i] + lb[i];
        float gi = sigmoidf_(gb[(0 * EE + c) * PIX + p]);
        float gf = sigmoidf_(gb[(1 * EE + c) * PIX + p]);
        float go = sigmoidf_(gb[(2 * EE + c) * PIX + p]);
        float gg = tanhf(gb[(3 * EE + c) * PIX + p]);
        float ga = sigmoidf_(gb[(4 * EE + c) * PIX + p]);
        float cn = gf * (cb[i] * nd) + gi * gg + ga * tanhf(aon);
        dst[i] = go * tanhf(cn);
    }
}

// ---------------- launch ----------------
extern "C" void kernel_launch(void* const* d_in, const int* in_sizes, int n_in,
                              void* d_out, int out_size) {
    const float* x       = (const float*)d_in[0];
    const float* h0      = (const float*)d_in[1];
    const float* c0      = (const float*)d_in[2];
    const float* k0      = (const float*)d_in[3];
    const float* v0      = (const float*)d_in[4];
    const void*  src_mask = d_in[5];
    const void*  notdone  = d_in[6];
    const float* main_w  = (const float*)d_in[7];
    const float* main_b  = (const float*)d_in[8];
    const float* proj_w  = (const float*)d_in[9];
    const float* proj_b  = (const float*)d_in[10];
    const float* out_w   = (const float*)d_in[11];
    const float* out_b   = (const float*)d_in[12];
    const float* ln_w    = (const float*)d_in[13];
    const float* ln_b    = (const float*)d_in[14];
    const float* pos_w   = (const float*)d_in[15];
    const float* pos_b   = (const float*)d_in[16];
    float* out = (float*)d_out;

    cudaFuncSetAttribute(conv_fused_kernel,
                         cudaFuncAttributeMaxDynamicSharedMemorySize, CONV_SMEM);

    detect_kernel<<<1, 256>>>((const int*)src_mask);
    bias_kernel<<<(BB * MEM + 255) / 256, 256>>>(src_mask, notdone);
    for (int n = 0; n < LNUM; n++) {
        int tot = BB * C_MAIN * PIX;
        prep_kernel<<<(tot + 255) / 256, 256>>>(x, h0, n, n == 0 ? 1 : 0);
        conv_fused_kernel<<<dim3(BB, 8), 256, CONV_SMEM>>>(main_w, main_b,
                                                           proj_w, proj_b, n);
        attn_kernel<<<dim3(BB, NHH), 256>>>(k0, v0, pos_w, pos_b, n);
        final_kernel<<<BB, 256>>>(out_w, out_b, ln_w, ln_b, c0, x, n,
                                  out, n == LNUM - 1 ? 1 : 0);
    }
}

// round 7
// speedup vs baseline: 1.1522x; 1.1522x over previous
#include <cuda_runtime.h>
#include <cstdint>

// Problem constants
#define LNUM 2
#define BB   128
#define CIN  64
#define EE   64
#define NHH  8
#define MEM  40
#define HD   8
#define THD  512         // HD*HW
#define PIX  64          // spatial size
#define C_MAIN 192       // CIN + 2E
#define C_PROJ 128       // CIN + E
#define CO_MAIN 320      // 5E
#define CO_PROJ 192      // 3E

#define PSTR  140        // u64 stride per channel-pair (10 rows x 14 u64)
#define SIN2_U64 (32 * PSTR)   // 4480 u64
#define WS2   37         // u64 stride per co (4 pairs x 9 used); 37*5 mod 16 distinct
#define WT2_U64 (64 * WS2)     // 2368 u64
#define CONV_SMEM ((SIN2_U64 + WT2_U64) * 8)   // 54784 B

typedef unsigned long long u64;

// ---------------- scratch (device globals; no allocation) ----------------
__device__ float g_inp  [BB * C_MAIN * PIX];   // (B,192,64)
__device__ float g_gates[BB * CO_MAIN * PIX];  // (B,320,64)
__device__ float g_kqv  [BB * CO_PROJ * PIX];  // (B,192,64)
__device__ float g_attn [BB * EE * PIX];       // (B,64,64)
__device__ float g_out  [BB * EE * PIX];       // (B,64,64)
__device__ float g_bias [BB * MEM];
__device__ float g_nd   [BB];
__device__ int   g_is_i32;

__device__ __forceinline__ float sigmoidf_(float v) {
    return 1.0f / (1.0f + __expf(-v));
}

// ---------------- packed f32x2 helpers (sm_103a) ----------------
__device__ __forceinline__ u64 fma2(u64 a, u64 b, u64 c) {
    u64 d;
    asm("fma.rn.f32x2 %0, %1, %2, %3;" : "=l"(d) : "l"(a), "l"(b), "l"(c));
    return d;
}
__device__ __forceinline__ float2 unpk(u64 v) {
    float2 r;
    asm("mov.b64 {%0, %1}, %2;" : "=f"(r.x), "=f"(r.y) : "l"(v));
    return r;
}

// ---------------- dtype detection for bool inputs (parallel) ----------------
__global__ void detect_kernel(const int* __restrict__ sm) {
    __shared__ int bad;
    if (threadIdx.x == 0) bad = 0;
    __syncthreads();
    int anybad = 0;
    for (int i = threadIdx.x; i < (BB * MEM) / 4; i += 256) {
        int v = sm[i];
        if (v != 0 && v != 1) anybad = 1;
    }
    if (anybad) bad = 1;
    __syncthreads();
    if (threadIdx.x == 0) g_is_i32 = !bad;
}

__device__ __forceinline__ int read_bool(const void* p, int idx) {
    if (g_is_i32) return ((const int*)p)[idx] != 0;
    return ((const unsigned char*)p)[idx] != 0;
}

// ---------------- bias + notdone ----------------
__global__ void bias_kernel(const void* __restrict__ src_mask,
                            const void* __restrict__ notdone) {
    int t = blockIdx.x * 256 + threadIdx.x;
    if (t < BB) g_nd[t] = read_bool(notdone, t) ? 1.0f : 0.0f;
    if (t >= BB * MEM) return;
    int b = t / MEM, m = t - b * MEM;
    float v;
    if (m == MEM - 1) {
        v = 3.0f;  // MASK_B
    } else {
        bool masked = read_bool(src_mask, b * MEM + m + 1) || !read_bool(notdone, b);
        v = masked ? -1e9f : 0.0f;
    }
    g_bias[t] = v;
}

// ---------------- build concat input (x | out | h*nd) ----------------
__global__ void prep_kernel(const float* __restrict__ x,
                            const float* __restrict__ h0,
                            int n, int first) {
    int idx = blockIdx.x * 256 + threadIdx.x;
    if (idx >= BB * C_MAIN * PIX) return;
    int b = idx / (C_MAIN * PIX);
    int r = idx - b * (C_MAIN * PIX);
    int c = r >> 6;
    int p = r & 63;
    float nd = g_nd[b];
    float v;
    if (c < CIN) {
        v = x[b * (CIN * PIX) + r];
    } else if (c < CIN + EE) {
        int off = b * (EE * PIX) + (c - CIN) * PIX + p;
        if (first)
            v = h0[((size_t)(LNUM - 1) * BB + b) * (EE * PIX) + (c - CIN) * PIX + p] * nd;
        else
            v = g_out[off];
    } else {
        v = h0[((size_t)n * BB + b) * (EE * PIX) + (c - CIN - EE) * PIX + p] * nd;
    }
    g_inp[idx] = v;
}

// ---------------- fused main(192->320) + proj(128->192) 3x3 SAME conv ----
// FFMA2 over CHANNEL PAIRS: input smem holds (even ch, odd ch) f32x2 per
// spatial cell; weights staged as (w_c, w_c+1) pairs. Inner loop is pure
// fma.rn.f32x2 with zero repacking; lo+hi summed once in the epilogue.
// grid = (B, 8): y<5 -> main co [64y,...), y>=5 -> proj co [64(y-5),...)
// 256 threads: (row = tid&7, cog = tid>>3) computes co = cobase+cog and
// co = cobase+cog+32 over 8 pixels of its row.
__global__ void __launch_bounds__(256, 3)
conv_fused_kernel(const float* __restrict__ main_w,
                  const float* __restrict__ main_b,
                  const float* __restrict__ proj_w,
                  const float* __restrict__ proj_b,
                  int n) {
    extern __shared__ u64 smem2[];
    u64* sin2 = smem2;              // 32 pairs x PSTR (10 rows x 14 u64)
    u64* wt2  = smem2 + SIN2_U64;   // 64 co x WS2 (4 pairs x 9 u64 used)

    int b = blockIdx.x;
    int y = blockIdx.y;
    bool ismain = (y < 5);
    int cobase = ismain ? y * 64 : (y - 5) * 64;
    int cin    = ismain ? C_MAIN : C_PROJ;
    int nchunk = cin >> 6;
    const float* wsrc = ismain
        ? main_w + (size_t)n * CO_MAIN * C_MAIN * 9
        : proj_w + (size_t)n * CO_PROJ * C_PROJ * 9;
    const float* inp = g_inp + (size_t)b * C_MAIN * PIX;

    int tid = threadIdx.x;
    int row = tid & 7;
    int cog = tid >> 3;       // 0..31
    int co_s = tid >> 2;      // staging: 4 threads per co
    int part = tid & 3;       // pair index within the 8-channel step

    u64 acc0[8], acc1[8];
#pragma unroll
    for (int xx = 0; xx < 8; xx++) { acc0[xx] = 0ull; acc1[xx] = 0ull; }

    // zero input smem once (padding cells stay 0)
    for (int i = tid; i < SIN2_U64; i += 256) sin2[i] = 0ull;

    for (int chunk = 0; chunk < nchunk; chunk++) {
        int c0 = chunk * 64;
        __syncthreads();   // previous compute done before refill
        // stage 32 channel-pairs as interleaved f32x2
        for (int i = tid; i < 32 * PIX; i += 256) {
            int q = i >> 6, p = i & 63;
            float lo = inp[(c0 + 2 * q) * PIX + p];
            float hi = inp[(c0 + 2 * q + 1) * PIX + p];
            int py = p >> 3, px = p & 7;
            *(float2*)&sin2[q * PSTR + (py + 1) * 14 + px + 1] = make_float2(lo, hi);
        }
        for (int cs = 0; cs < 64; cs += 8) {   // 4 channel-pairs per step
            __syncthreads();   // prior compute done / input ready
            {
                // stage packed weights: co_s, pair = part -> channels cs+2p, cs+2p+1
                const float* s0 = wsrc + (size_t)(cobase + co_s) * cin * 9
                                       + (c0 + cs + 2 * part) * 9;
                float2* d = (float2*)&wt2[co_s * WS2 + part * 9];
#pragma unroll
                for (int k = 0; k < 9; k++)
                    d[k] = make_float2(s0[k], s0[9 + k]);
            }
            __syncthreads();
#pragma unroll
            for (int pr = 0; pr < 4; pr++) {
                const u64* sp = sin2 + ((cs >> 1) + pr) * PSTR;
                const u64* W0 = wt2 + cog * WS2 + pr * 9;
                const u64* W1 = wt2 + (cog + 32) * WS2 + pr * 9;
#pragma unroll
                for (int r = 0; r < 3; r++) {
                    const u64* s = sp + (row + r) * 14;
                    u64 rv[10];
#pragma unroll
                    for (int j = 0; j < 5; j++) {
                        ulonglong2 t = ((const ulonglong2*)s)[j];
                        rv[2 * j] = t.x; rv[2 * j + 1] = t.y;
                    }
                    u64 wa0 = W0[r * 3 + 0], wa1 = W0[r * 3 + 1], wa2 = W0[r * 3 + 2];
                    u64 wb0 = W1[r * 3 + 0], wb1 = W1[r * 3 + 1], wb2 = W1[r * 3 + 2];
#pragma unroll
                    for (int xx = 0; xx < 8; xx++)
                        acc0[xx] = fma2(rv[xx], wa0, acc0[xx]);
#pragma unroll
                    for (int xx = 0; xx < 8; xx++)
                        acc0[xx] = fma2(rv[xx + 1], wa1, acc0[xx]);
#pragma unroll
                    for (int xx = 0; xx < 8; xx++)
                        acc0[xx] = fma2(rv[xx + 2], wa2, acc0[xx]);
#pragma unroll
                    for (int xx = 0; xx < 8; xx++)
                        acc1[xx] = fma2(rv[xx], wb0, acc1[xx]);
#pragma unroll
                    for (int xx = 0; xx < 8; xx++)
                        acc1[xx] = fma2(rv[xx + 1], wb1, acc1[xx]);
#pragma unroll
                    for (int xx = 0; xx < 8; xx++)
                        acc1[xx] = fma2(rv[xx + 2], wb2, acc1[xx]);
                }
            }
        }
    }

    int co0 = cobase + cog;
    int co1 = cobase + cog + 32;
    float o8[8];
    if (ismain) {
        float b0 = main_b[n * CO_MAIN + co0];
        float b1 = main_b[n * CO_MAIN + co1];
        float* o0 = g_gates + ((size_t)b * CO_MAIN + co0) * PIX + row * 8;
        float* o1 = g_gates + ((size_t)b * CO_MAIN + co1) * PIX + row * 8;
#pragma unroll
        for (int xx = 0; xx < 8; xx++) {
            float2 u = unpk(acc0[xx]);
            o8[xx] = u.x + u.y + b0;
        }
        *(float4*)(o0 + 0) = *(float4*)(o8 + 0);
        *(float4*)(o0 + 4) = *(float4*)(o8 + 4);
#pragma unroll
        for (int xx = 0; xx < 8; xx++) {
            float2 u = unpk(acc1[xx]);
            o8[xx] = u.x + u.y + b1;
        }
        *(float4*)(o1 + 0) = *(float4*)(o8 + 0);
        *(float4*)(o1 + 4) = *(float4*)(o8 + 4);
    } else {
        float b0 = proj_b[n * CO_PROJ + co0];
        float b1 = proj_b[n * CO_PROJ + co1];
        float* o0 = g_kqv + ((size_t)b * CO_PROJ + co0) * PIX + row * 8;
        float* o1 = g_kqv + ((size_t)b * CO_PROJ + co1) * PIX + row * 8;
#pragma unroll
        for (int xx = 0; xx < 8; xx++) {
            float2 u = unpk(acc0[xx]);
            o8[xx] = u.x + u.y + b0;
        }
        *(float4*)(o0 + 0) = *(float4*)(o8 + 0);
        *(float4*)(o0 + 4) = *(float4*)(o8 + 4);
#pragma unroll
        for (int xx = 0; xx < 8; xx++) {
            float2 u = unpk(acc1[xx]);
            o8[xx] = u.x + u.y + b1;
        }
        *(float4*)(o1 + 0) = *(float4*)(o8 + 0);
        *(float4*)(o1 + 4) = *(float4*)(o8 + 4);
    }
}

// ---------------- attention over rolling memory ----------------
__global__ void attn_kernel(const float* __restrict__ k0,
                            const float* __restrict__ v0,
                            const float* __restrict__ pos_w,
                            const float* __restrict__ pos_b,
                            int n) {
    int b = blockIdx.x;
    int h = blockIdx.y;
    int tid = threadIdx.x;
    __shared__ float q[THD], kn[THD], vn[THD];
    __shared__ float sc[MEM], wts[MEM];

    const float* kqv = g_kqv + (size_t)b * CO_PROJ * PIX;
    const float rscale = 0.044194173824159216f;  // 1/sqrt(512)
    for (int d = tid; d < THD; d += 256) {
        int hd = d >> 6, hw = d & 63;
        kn[d] = kqv[(h * 24 + hd) * PIX + hw];
        q[d]  = kqv[(h * 24 + 8 + hd) * PIX + hw] * rscale;
        vn[d] = kqv[(h * 24 + 16 + hd) * PIX + hw];
    }
    __syncthreads();

    const float* kb  = k0 + ((((size_t)n * BB + b) * NHH + h) * MEM) * THD;
    const float* pwb = pos_w + (size_t)n * MEM * (NHH * THD) + h * THD;
    int warp = tid >> 5, lane = tid & 31;
    for (int m = warp; m < MEM; m += 8) {
        const float* kr = (m < MEM - 1) ? (kb + (size_t)(m + 1) * THD) : kn;
        const float* pr = pwb + (size_t)m * (NHH * THD);
        float p = 0.0f;
        for (int d = lane; d < THD; d += 32)
            p = fmaf(q[d], kr[d] + pr[d], p);
#pragma unroll
        for (int o = 16; o; o >>= 1) p += __shfl_xor_sync(0xffffffffu, p, o);
        if (lane == 0)
            sc[m] = p + g_bias[b * MEM + m] + pos_b[(size_t)n * MEM * NHH + m * NHH + h];
    }
    __syncthreads();
    if (tid == 0) {
        float mx = sc[0];
#pragma unroll
        for (int m = 1; m < MEM; m++) mx = fmaxf(mx, sc[m]);
        float s = 0.0f;
#pragma unroll
        for (int m = 0; m < MEM; m++) {
            float e = __expf(sc[m] - mx);
            wts[m] = e;
            s += e;
        }
        float inv = 1.0f / s;
#pragma unroll
        for (int m = 0; m < MEM; m++) wts[m] *= inv;
    }
    __syncthreads();

    const float* vb = v0 + ((((size_t)n * BB + b) * NHH + h) * MEM) * THD;
    for (int d = tid; d < THD; d += 256) {
        float acc = wts[MEM - 1] * vn[d];
        for (int m = 0; m < MEM - 1; m++)
            acc = fmaf(wts[m], vb[(size_t)(m + 1) * THD + d], acc);
        int hd = d >> 6, hw = d & 63;
        g_attn[(size_t)b * (EE * PIX) + (h * 8 + hd) * PIX + hw] = acc;
    }
}

// ---------------- out conv + residual + layernorm + LSTM combine ---------
__global__ void final_kernel(const float* __restrict__ out_w,
                             const float* __restrict__ out_b,
                             const float* __restrict__ ln_w,
                             const float* __restrict__ ln_b,
                             const float* __restrict__ c0,
                             const float* __restrict__ x,
                             int n, float* __restrict__ dst_last, int last) {
    __shared__ float sa[EE * 100];   // padded attn input
    __shared__ float ao[EE * PIX];   // conv+residual result
    __shared__ float red[16];
    __shared__ float s_mu, s_rv;
    int b = blockIdx.x;
    int tid = threadIdx.x;

    for (int i = tid; i < EE * 100; i += 256) sa[i] = 0.0f;
    __syncthreads();
    const float* at = g_attn + (size_t)b * EE * PIX;
    for (int i = tid; i < EE * PIX; i += 256) {
        int c = i >> 6, p = i & 63;
        sa[c * 100 + ((p >> 3) + 1) * 10 + (p & 7) + 1] = at[i];
    }
    __syncthreads();

    const float* wb = out_w + (size_t)n * EE * EE * 9;
    const float* xr = x + (size_t)b * EE * PIX;
    for (int t = tid; t < EE * 8; t += 256) {
        int co = t >> 3;
        int row = t & 7;
        const float* wc = wb + (size_t)co * EE * 9;
        float acc[8];
#pragma unroll
        for (int xx = 0; xx < 8; xx++) acc[xx] = 0.0f;
        for (int c = 0; c < EE; c++) {
            const float* s = sa + c * 100 + row * 10;
            const float* w = wc + c * 9;
            float w0 = w[0], w1 = w[1], w2 = w[2];
            float w3 = w[3], w4 = w[4], w5 = w[5];
            float w6 = w[6], w7 = w[7], w8 = w[8];
#pragma unroll
            for (int xx = 0; xx < 8; xx++) {
                float a = acc[xx];
                a = fmaf(s[xx],      w0, a);
                a = fmaf(s[xx + 1],  w1, a);
                a = fmaf(s[xx + 2],  w2, a);
                a = fmaf(s[10 + xx],     w3, a);
                a = fmaf(s[10 + xx + 1], w4, a);
                a = fmaf(s[10 + xx + 2], w5, a);
                a = fmaf(s[20 + xx],     w6, a);
                a = fmaf(s[20 + xx + 1], w7, a);
                a = fmaf(s[20 + xx + 2], w8, a);
                acc[xx] = a;
            }
        }
        float bb = out_b[n * EE + co];
        int base = co * PIX + row * 8;
#pragma unroll
        for (int xx = 0; xx < 8; xx++)
            ao[base + xx] = acc[xx] + bb + xr[base + xx];
    }
    __syncthreads();

    float s1 = 0.0f, s2 = 0.0f;
    for (int i = tid; i < EE * PIX; i += 256) {
        float v = ao[i];
        s1 += v;
        s2 += v * v;
    }
    int warp = tid >> 5, lane = tid & 31;
#pragma unroll
    for (int o = 16; o; o >>= 1) {
        s1 += __shfl_xor_sync(0xffffffffu, s1, o);
        s2 += __shfl_xor_sync(0xffffffffu, s2, o);
    }
    if (lane == 0) { red[warp] = s1; red[8 + warp] = s2; }
    __syncthreads();
    if (tid == 0) {
        float a = 0.0f, q2 = 0.0f;
#pragma unroll
        for (int w2 = 0; w2 < 8; w2++) { a += red[w2]; q2 += red[8 + w2]; }
        float mu = a * (1.0f / 4096.0f);
        float var = q2 * (1.0f / 4096.0f) - mu * mu;
        s_mu = mu;
        s_rv = rsqrtf(var + 1e-5f);
    }
    __syncthreads();
    float mu = s_mu, rv = s_rv;

    const float* gb = g_gates + (size_t)b * CO_MAIN * PIX;
    const float* cb = c0 + ((size_t)n * BB + b) * (EE * PIX);
    float nd = g_nd[b];
    float* dst = (last ? dst_last : g_out) + (size_t)b * EE * PIX;
    const float* lw = ln_w + (size_t)n * EE * PIX;
    const float* lb = ln_b + (size_t)n * EE * PIX;
    for (int i = tid; i < EE * PIX; i += 256) {
        int c = i >> 6, p = i & 63;
        float aon = (ao[i] - mu) * rv * lw[i] + lb[i];
        float gi = sigmoidf_(gb[(0 * EE + c) * PIX + p]);
        float gf = sigmoidf_(gb[(1 * EE + c) * PIX + p]);
        float go = sigmoidf_(gb[(2 * EE + c) * PIX + p]);
        float gg = tanhf(gb[(3 * EE + c) * PIX + p]);
        float ga = sigmoidf_(gb[(4 * EE + c) * PIX + p]);
        float cn = gf * (cb[i] * nd) + gi * gg + ga * tanhf(aon);
        dst[i] = go * tanhf(cn);
    }
}

// ---------------- launch ----------------
extern "C" void kernel_launch(void* const* d_in, const int* in_sizes, int n_in,
                              void* d_out, int out_size) {
    const float* x       = (const float*)d_in[0];
    const float* h0      = (const float*)d_in[1];
    const float* c0      = (const float*)d_in[2];
    const float* k0      = (const float*)d_in[3];
    const float* v0      = (const float*)d_in[4];
    const void*  src_mask = d_in[5];
    const void*  notdone  = d_in[6];
    const float* main_w  = (const float*)d_in[7];
    const float* main_b  = (const float*)d_in[8];
    const float* proj_w  = (const float*)d_in[9];
    const float* proj_b  = (const float*)d_in[10];
    const float* out_w   = (const float*)d_in[11];
    const float* out_b   = (const float*)d_in[12];
    const float* ln_w    = (const float*)d_in[13];
    const float* ln_b    = (const float*)d_in[14];
    const float* pos_w   = (const float*)d_in[15];
    const float* pos_b   = (const float*)d_in[16];
    float* out = (float*)d_out;

    cudaFuncSetAttribute(conv_fused_kernel,
                         cudaFuncAttributeMaxDynamicSharedMemorySize, CONV_SMEM);

    detect_kernel<<<1, 256>>>((const int*)src_mask);
    bias_kernel<<<(BB * MEM + 255) / 256, 256>>>(src_mask, notdone);
    for (int n = 0; n < LNUM; n++) {
        int tot = BB * C_MAIN * PIX;
        prep_kernel<<<(tot + 255) / 256, 256>>>(x, h0, n, n == 0 ? 1 : 0);
        conv_fused_kernel<<<dim3(BB, 8), 256, CONV_SMEM>>>(main_w, main_b,
                                                           proj_w, proj_b, n);
        attn_kernel<<<dim3(BB, NHH), 256>>>(k0, v0, pos_w, pos_b, n);
        final_kernel<<<BB, 256>>>(out_w, out_b, ln_w, ln_b, c0, x, n,
                                  out, n == LNUM - 1 ? 1 : 0);
    }
}

// round 9
// speedup vs baseline: 1.4864x; 1.2901x over previous
#include <cuda_runtime.h>
#include <cuda_bf16.h>
#include <cstdint>

// Problem constants
#define LNUM 2
#define BB   128
#define CIN  64
#define EE   64
#define NHH  8
#define MEM  40
#define HD   8
#define THD  512         // HD*HW
#define PIX  64          // spatial size
#define C_MAIN 192       // CIN + 2E
#define C_PROJ 128       // CIN + E
#define CO_MAIN 320      // 5E
#define CO_PROJ 192      // 3E

// ---- warp-MMA GEMM config ----
// Fused GEMM: M=512 (320 main co + 192 proj co, proj zero-padded over c>=128),
// N=8192 (128 b x 64 px), K=1728 (9 taps x 192 ch).
// Block: 256 thr (8 warps as 4m x 2n), tile M=128 x N=128 (2 batches), K chunk 64.
#define NCHUNK 27
#define ASTR 72                 // padded bf16 row stride (36 words % 32 = 4)
#define SA_ELEMS (128 * ASTR)   // 9216 bf16
#define MMA_SMEM (4 * SA_ELEMS * 2)   // 73728 B (A hi/lo + B hi/lo)

// ---------------- scratch (device globals; no allocation) ----------------
__device__ float g_inp  [BB * C_MAIN * PIX];   // (B,192,64)
__device__ float g_gates[BB * CO_MAIN * PIX];  // (B,320,64)
__device__ float g_kqv  [BB * CO_PROJ * PIX];  // (B,192,64)
__device__ float g_attn [BB * EE * PIX];       // (B,64,64)
__device__ float g_out  [BB * EE * PIX];       // (B,64,64)
__device__ float g_bias [BB * MEM];
__device__ float g_nd   [BB];
__device__ int   g_is_i32;
// pre-split bf16 weight tiles, plain [128 r][64 k]: [layer][mtile][chunk]
__device__ __nv_bfloat16 g_wA_hi[2 * 4 * NCHUNK * 8192];
__device__ __nv_bfloat16 g_wA_lo[2 * 4 * NCHUNK * 8192];

__device__ __forceinline__ float sigmoidf_(float v) {
    return 1.0f / (1.0f + __expf(-v));
}

__device__ __forceinline__ uint32_t smem_to_u32(const void* p) {
    uint32_t a;
    asm("{ .reg .u64 t; cvta.to.shared.u64 t, %1; cvt.u32.u64 %0, t; }"
        : "=r"(a) : "l"(p));
    return a;
}
__device__ __forceinline__ void ldsm4(uint32_t addr, uint32_t* r) {
    asm volatile("ldmatrix.sync.aligned.m8n8.x4.shared.b16 {%0,%1,%2,%3}, [%4];"
        : "=r"(r[0]), "=r"(r[1]), "=r"(r[2]), "=r"(r[3]) : "r"(addr));
}
__device__ __forceinline__ void mma16816(float* d, const uint32_t* a,
                                         uint32_t b0, uint32_t b1) {
    asm volatile(
        "mma.sync.aligned.m16n8k16.row.col.f32.bf16.bf16.f32 "
        "{%0,%1,%2,%3}, {%4,%5,%6,%7}, {%8,%9}, {%0,%1,%2,%3};"
        : "+f"(d[0]), "+f"(d[1]), "+f"(d[2]), "+f"(d[3])
        : "r"(a[0]), "r"(a[1]), "r"(a[2]), "r"(a[3]), "r"(b0), "r"(b1));
}

// ---------------- dtype detection for bool inputs (parallel) ----------------
__global__ void detect_kernel(const int* __restrict__ sm) {
    __shared__ int bad;
    if (threadIdx.x == 0) bad = 0;
    __syncthreads();
    int anybad = 0;
    for (int i = threadIdx.x; i < (BB * MEM) / 4; i += 256) {
        int v = sm[i];
        if (v != 0 && v != 1) anybad = 1;
    }
    if (anybad) bad = 1;
    __syncthreads();
    if (threadIdx.x == 0) g_is_i32 = !bad;
}

__device__ __forceinline__ int read_bool(const void* p, int idx) {
    if (g_is_i32) return ((const int*)p)[idx] != 0;
    return ((const unsigned char*)p)[idx] != 0;
}

// ---------------- bias + notdone ----------------
__global__ void bias_kernel(const void* __restrict__ src_mask,
                            const void* __restrict__ notdone) {
    int t = blockIdx.x * 256 + threadIdx.x;
    if (t < BB) g_nd[t] = read_bool(notdone, t) ? 1.0f : 0.0f;
    if (t >= BB * MEM) return;
    int b = t / MEM, m = t - b * MEM;
    float v;
    if (m == MEM - 1) {
        v = 3.0f;  // MASK_B
    } else {
        bool masked = read_bool(src_mask, b * MEM + m + 1) || !read_bool(notdone, b);
        v = masked ? -1e9f : 0.0f;
    }
    g_bias[t] = v;
}

// ---------------- weight prepass: bf16 hi/lo split, plain tiles ----------
// blockIdx.x = ((layer*4 + mtile)*27 + chunk), 216 blocks.
__global__ void wprep_kernel(const float* __restrict__ main_w,
                             const float* __restrict__ proj_w) {
    int id = blockIdx.x;
    int n = id / (4 * NCHUNK);
    int r2 = id % (4 * NCHUNK);
    int mtile = r2 / NCHUNK;
    int chunk = r2 % NCHUNK;
    int t  = chunk / 3;
    int c0 = (chunk % 3) * 64;
    __nv_bfloat16* dh = g_wA_hi + (size_t)id * 8192;
    __nv_bfloat16* dl = g_wA_lo + (size_t)id * 8192;
    for (int e = threadIdx.x; e < 8192; e += 256) {
        int r = e >> 6, kk = e & 63;
        int c = c0 + kk;
        int gco = mtile * 128 + r;
        float w = 0.0f;
        if (gco < CO_MAIN) {
            w = main_w[(((size_t)n * CO_MAIN + gco) * C_MAIN + c) * 9 + t];
        } else if (c < C_PROJ) {
            w = proj_w[(((size_t)n * CO_PROJ + (gco - CO_MAIN)) * C_PROJ + c) * 9 + t];
        }
        __nv_bfloat16 h = __float2bfloat16(w);
        __nv_bfloat16 l = __float2bfloat16(w - __bfloat162float(h));
        dh[e] = h;
        dl[e] = l;
    }
}

// ---------------- build concat input (x | out | h*nd) ----------------
__global__ void prep_kernel(const float* __restrict__ x,
                            const float* __restrict__ h0,
                            int n, int first) {
    int idx = blockIdx.x * 256 + threadIdx.x;
    if (idx >= BB * C_MAIN * PIX) return;
    int b = idx / (C_MAIN * PIX);
    int r = idx - b * (C_MAIN * PIX);
    int c = r >> 6;
    int p = r & 63;
    float nd = g_nd[b];
    float v;
    if (c < CIN) {
        v = x[b * (CIN * PIX) + r];
    } else if (c < CIN + EE) {
        int off = b * (EE * PIX) + (c - CIN) * PIX + p;
        if (first)
            v = h0[((size_t)(LNUM - 1) * BB + b) * (EE * PIX) + (c - CIN) * PIX + p] * nd;
        else
            v = g_out[off];
    } else {
        v = h0[((size_t)n * BB + b) * (EE * PIX) + (c - CIN - EE) * PIX + p] * nd;
    }
    g_inp[idx] = v;
}

// ---------------- warp-MMA fused conv GEMM ----------------
// grid (64 n-tiles, 4 m-tiles), 256 threads = 8 warps (4m x 2n).
// Warp tile 32 rows x 64 cols; 3-term bf16 split accumulated in fp32.
__global__ void __launch_bounds__(256, 1)
conv_mma_kernel(const float* __restrict__ main_b,
                const float* __restrict__ proj_b,
                int n) {
    extern __shared__ __nv_bfloat16 smb[];
    __nv_bfloat16* sAh = smb;
    __nv_bfloat16* sAl = smb + SA_ELEMS;
    __nv_bfloat16* sBh = smb + 2 * SA_ELEMS;
    __nv_bfloat16* sBl = smb + 3 * SA_ELEMS;

    int tid = threadIdx.x;
    int lane = tid & 31, w = tid >> 5;
    int ntile = blockIdx.x, mtile = blockIdx.y;
    int b0 = ntile * 2;
    int mrow0 = (w >> 1) * 32;
    int nc0 = (w & 1) * 64;

    float acc[2][8][4];
#pragma unroll
    for (int mi = 0; mi < 2; mi++)
#pragma unroll
        for (int ni = 0; ni < 8; ni++)
#pragma unroll
            for (int j = 0; j < 4; j++) acc[mi][ni][j] = 0.0f;

    uint32_t sAh_u = smem_to_u32(sAh), sAl_u = smem_to_u32(sAl);
    uint32_t sBh_u = smem_to_u32(sBh), sBl_u = smem_to_u32(sBl);
    int lr = lane & 15, lc = lane >> 4;
    uint32_t aoff = (uint32_t)(((mrow0 + lr) * ASTR + lc * 8) * 2);
    uint32_t boff = (uint32_t)(((nc0 + lr) * ASTR + lc * 8) * 2);

    // B-staging geometry (thread -> one B row, 32 channels)
    int brow = tid >> 1, half = tid & 1;
    int bb = brow >> 6, px = brow & 63;
    int yy = px >> 3, xx = px & 7;

    for (int chunk = 0; chunk < NCHUNK; chunk++) {
        int t  = chunk / 3;
        int c0 = (chunk % 3) * 64;
        int ty = t / 3, tx = t % 3;
        __syncthreads();   // previous chunk's compute done before overwrite

        // ---- stage A (plain copy, pad to ASTR) ----
        {
            size_t toff = (((size_t)n * 4 + mtile) * NCHUNK + chunk) * 8192;
            const uint4* shh = (const uint4*)(g_wA_hi + toff);
            const uint4* sll = (const uint4*)(g_wA_lo + toff);
            for (int i = tid; i < 1024; i += 256) {
                int r = i >> 3, c = i & 7;
                *(uint4*)&sAh[r * ASTR + c * 8] = shh[i];
                *(uint4*)&sAl[r * ASTR + c * 8] = sll[i];
            }
        }
        // ---- stage B (im2col gather + bf16 hi/lo split) ----
        {
            int iy = yy + ty - 1, ix = xx + tx - 1;
            bool valid = ((unsigned)iy < 8u) && ((unsigned)ix < 8u);
            const float* src = g_inp
                + ((size_t)(b0 + bb) * C_MAIN + c0 + half * 32) * PIX
                + (valid ? iy * 8 + ix : 0);
            __nv_bfloat16* dh = sBh + brow * ASTR + half * 32;
            __nv_bfloat16* dl = sBl + brow * ASTR + half * 32;
#pragma unroll
            for (int j = 0; j < 32; j += 2) {
                float v0 = valid ? src[j * PIX] : 0.0f;
                float v1 = valid ? src[(j + 1) * PIX] : 0.0f;
                __nv_bfloat16 h0 = __float2bfloat16(v0);
                __nv_bfloat16 h1 = __float2bfloat16(v1);
                __nv_bfloat16 l0 = __float2bfloat16(v0 - __bfloat162float(h0));
                __nv_bfloat16 l1 = __float2bfloat16(v1 - __bfloat162float(h1));
                unsigned hp = (unsigned)__bfloat16_as_ushort(h0)
                            | ((unsigned)__bfloat16_as_ushort(h1) << 16);
                unsigned lp = (unsigned)__bfloat16_as_ushort(l0)
                            | ((unsigned)__bfloat16_as_ushort(l1) << 16);
                *(unsigned*)&dh[j] = hp;
                *(unsigned*)&dl[j] = lp;
            }
        }
        __syncthreads();

        // ---- compute: 4 K-steps x (2 m x 8 n) x 3 split terms ----
#pragma unroll
        for (int ks = 0; ks < 4; ks++) {
            uint32_t kb = (uint32_t)(ks * 32);   // 16 bf16 = 32 bytes
            uint32_t ah[2][4], al[2][4], bh[4][4], bl[4][4];
            ldsm4(sAh_u + aoff + kb, ah[0]);
            ldsm4(sAh_u + aoff + 16 * ASTR * 2 + kb, ah[1]);
            ldsm4(sAl_u + aoff + kb, al[0]);
            ldsm4(sAl_u + aoff + 16 * ASTR * 2 + kb, al[1]);
#pragma unroll
            for (int pn = 0; pn < 4; pn++) {
                ldsm4(sBh_u + boff + pn * 16 * ASTR * 2 + kb, bh[pn]);
                ldsm4(sBl_u + boff + pn * 16 * ASTR * 2 + kb, bl[pn]);
            }
#pragma unroll
            for (int mi = 0; mi < 2; mi++) {
#pragma unroll
                for (int ni = 0; ni < 8; ni++) {
                    int pn = ni >> 1, o = ni & 1;
                    mma16816(acc[mi][ni], ah[mi], bh[pn][o], bh[pn][o + 2]);
                    mma16816(acc[mi][ni], ah[mi], bl[pn][o], bl[pn][o + 2]);
                    mma16816(acc[mi][ni], al[mi], bh[pn][o], bh[pn][o + 2]);
                }
            }
        }
    }

    // ---- epilogue: bias add + direct stores ----
    int batch = b0 + (w & 1);
#pragma unroll
    for (int mi = 0; mi < 2; mi++) {
#pragma unroll
        for (int rr = 0; rr < 2; rr++) {
            int r = mrow0 + mi * 16 + rr * 8 + (lane >> 2);
            int gr = mtile * 128 + r;
            bool ismain = (gr < CO_MAIN);
            float bias = ismain ? main_b[n * CO_MAIN + gr]
                                : proj_b[n * CO_PROJ + (gr - CO_MAIN)];
            float* dst = ismain
                ? g_gates + ((size_t)batch * CO_MAIN + gr) * PIX
                : g_kqv  + ((size_t)batch * CO_PROJ + (gr - CO_MAIN)) * PIX;
#pragma unroll
            for (int ni = 0; ni < 8; ni++) {
                int pxc = ni * 8 + (lane & 3) * 2;
                float2 v;
                v.x = acc[mi][ni][rr * 2 + 0] + bias;
                v.y = acc[mi][ni][rr * 2 + 1] + bias;
                *(float2*)&dst[pxc] = v;
            }
        }
    }
}

// ---------------- attention over rolling memory ----------------
__global__ void attn_kernel(const float* __restrict__ k0,
                            const float* __restrict__ v0,
                            const float* __restrict__ pos_w,
                            const float* __restrict__ pos_b,
                            int n) {
    int b = blockIdx.x;
    int h = blockIdx.y;
    int tid = threadIdx.x;
    __shared__ float q[THD], kn[THD], vn[THD];
    __shared__ float sc[MEM], wts[MEM];

    const float* kqv = g_kqv + (size_t)b * CO_PROJ * PIX;
    const float rscale = 0.044194173824159216f;  // 1/sqrt(512)
    for (int d = tid; d < THD; d += 256) {
        int hd = d >> 6, hw = d & 63;
        kn[d] = kqv[(h * 24 + hd) * PIX + hw];
        q[d]  = kqv[(h * 24 + 8 + hd) * PIX + hw] * rscale;
        vn[d] = kqv[(h * 24 + 16 + hd) * PIX + hw];
    }
    __syncthreads();

    const float* kb  = k0 + ((((size_t)n * BB + b) * NHH + h) * MEM) * THD;
    const float* pwb = pos_w + (size_t)n * MEM * (NHH * THD) + h * THD;
    int warp = tid >> 5, lane = tid & 31;
    for (int m = warp; m < MEM; m += 8) {
        const float* kr = (m < MEM - 1) ? (kb + (size_t)(m + 1) * THD) : kn;
        const float* pr = pwb + (size_t)m * (NHH * THD);
        float p = 0.0f;
        for (int d = lane; d < THD; d += 32)
            p = fmaf(q[d], kr[d] + pr[d], p);
#pragma unroll
        for (int o = 16; o; o >>= 1) p += __shfl_xor_sync(0xffffffffu, p, o);
        if (lane == 0)
            sc[m] = p + g_bias[b * MEM + m] + pos_b[(size_t)n * MEM * NHH + m * NHH + h];
    }
    __syncthreads();
    if (tid == 0) {
        float mx = sc[0];
#pragma unroll
        for (int m = 1; m < MEM; m++) mx = fmaxf(mx, sc[m]);
        float s = 0.0f;
#pragma unroll
        for (int m = 0; m < MEM; m++) {
            float e = __expf(sc[m] - mx);
            wts[m] = e;
            s += e;
        }
        float inv = 1.0f / s;
#pragma unroll
        for (int m = 0; m < MEM; m++) wts[m] *= inv;
    }
    __syncthreads();

    const float* vb = v0 + ((((size_t)n * BB + b) * NHH + h) * MEM) * THD;
    for (int d = tid; d < THD; d += 256) {
        float acc = wts[MEM - 1] * vn[d];
        for (int m = 0; m < MEM - 1; m++)
            acc = fmaf(wts[m], vb[(size_t)(m + 1) * THD + d], acc);
        int hd = d >> 6, hw = d & 63;
        g_attn[(size_t)b * (EE * PIX) + (h * 8 + hd) * PIX + hw] = acc;
    }
}

// ---------------- out conv + residual + layernorm + LSTM combine ---------
__global__ void final_kernel(const float* __restrict__ out_w,
                             const float* __restrict__ out_b,
                             const float* __restrict__ ln_w,
                             const float* __restrict__ ln_b,
                             const float* __restrict__ c0,
                             const float* __restrict__ x,
                             int n, float* __restrict__ dst_last, int last) {
    __shared__ float sa[EE * 100];   // padded attn input
    __shared__ float ao[EE * PIX];   // conv+residual result
    __shared__ float red[16];
    __shared__ float s_mu, s_rv;
    int b = blockIdx.x;
    int tid = threadIdx.x;

    for (int i = tid; i < EE * 100; i += 256) sa[i] = 0.0f;
    __syncthreads();
    const float* at = g_attn + (size_t)b * EE * PIX;
    for (int i = tid; i < EE * PIX; i += 256) {
        int c = i >> 6, p = i & 63;
        sa[c * 100 + ((p >> 3) + 1) * 10 + (p & 7) + 1] = at[i];
    }
    __syncthreads();

    const float* wb = out_w + (size_t)n * EE * EE * 9;
    const float* xr = x + (size_t)b * EE * PIX;
    for (int t = tid; t < EE * 8; t += 256) {
        int co = t >> 3;
        int row = t & 7;
        const float* wc = wb + (size_t)co * EE * 9;
        float acc[8];
#pragma unroll
        for (int xx = 0; xx < 8; xx++) acc[xx] = 0.0f;
        for (int c = 0; c < EE; c++) {
            const float* s = sa + c * 100 + row * 10;
            const float* w = wc + c * 9;
            float w0 = w[0], w1 = w[1], w2 = w[2];
            float w3 = w[3], w4 = w[4], w5 = w[5];
            float w6 = w[6], w7 = w[7], w8 = w[8];
#pragma unroll
            for (int xx = 0; xx < 8; xx++) {
                float a = acc[xx];
                a = fmaf(s[xx],      w0, a);
                a = fmaf(s[xx + 1],  w1, a);
                a = fmaf(s[xx + 2],  w2, a);
                a = fmaf(s[10 + xx],     w3, a);
                a = fmaf(s[10 + xx + 1], w4, a);
                a = fmaf(s[10 + xx + 2], w5, a);
                a = fmaf(s[20 + xx],     w6, a);
                a = fmaf(s[20 + xx + 1], w7, a);
                a = fmaf(s[20 + xx + 2], w8, a);
                acc[xx] = a;
            }
        }
        float bb = out_b[n * EE + co];
        int base = co * PIX + row * 8;
#pragma unroll
        for (int xx = 0; xx < 8; xx++)
            ao[base + xx] = acc[xx] + bb + xr[base + xx];
    }
    __syncthreads();

    float s1 = 0.0f, s2 = 0.0f;
    for (int i = tid; i < EE * PIX; i += 256) {
        float v = ao[i];
        s1 += v;
        s2 += v * v;
    }
    int warp = tid >> 5, lane = tid & 31;
#pragma unroll
    for (int o = 16; o; o >>= 1) {
        s1 += __shfl_xor_sync(0xffffffffu, s1, o);
        s2 += __shfl_xor_sync(0xffffffffu, s2, o);
    }
    if (lane == 0) { red[warp] = s1; red[8 + warp] = s2; }
    __syncthreads();
    if (tid == 0) {
        float a = 0.0f, q2 = 0.0f;
#pragma unroll
        for (int w2 = 0; w2 < 8; w2++) { a += red[w2]; q2 += red[8 + w2]; }
        float mu = a * (1.0f / 4096.0f);
        float var = q2 * (1.0f / 4096.0f) - mu * mu;
        s_mu = mu;
        s_rv = rsqrtf(var + 1e-5f);
    }
    __syncthreads();
    float mu = s_mu, rv = s_rv;

    const float* gb = g_gates + (size_t)b * CO_MAIN * PIX;
    const float* cb = c0 + ((size_t)n * BB + b) * (EE * PIX);
    float nd = g_nd[b];
    float* dst = (last ? dst_last : g_out) + (size_t)b * EE * PIX;
    const float* lw = ln_w + (size_t)n * EE * PIX;
    const float* lb = ln_b + (size_t)n * EE * PIX;
    for (int i = tid; i < EE * PIX; i += 256) {
        int c = i >> 6, p = i & 63;
        float aon = (ao[i] - mu) * rv * lw[i] + lb[i];
        float gi = sigmoidf_(gb[(0 * EE + c) * PIX + p]);
        float gf = sigmoidf_(gb[(1 * EE + c) * PIX + p]);
        float go = sigmoidf_(gb[(2 * EE + c) * PIX + p]);
        float gg = tanhf(gb[(3 * EE + c) * PIX + p]);
        float ga = sigmoidf_(gb[(4 * EE + c) * PIX + p]);
        float cn = gf * (cb[i] * nd) + gi * gg + ga * tanhf(aon);
        dst[i] = go * tanhf(cn);
    }
}

// ---------------- launch ----------------
extern "C" void kernel_launch(void* const* d_in, const int* in_sizes, int n_in,
                              void* d_out, int out_size) {
    const float* x       = (const float*)d_in[0];
    const float* h0      = (const float*)d_in[1];
    const float* c0      = (const float*)d_in[2];
    const float* k0      = (const float*)d_in[3];
    const float* v0      = (const float*)d_in[4];
    const void*  src_mask = d_in[5];
    const void*  notdone  = d_in[6];
    const float* main_w  = (const float*)d_in[7];
    const float* main_b  = (const float*)d_in[8];
    const float* proj_w  = (const float*)d_in[9];
    const float* proj_b  = (const float*)d_in[10];
    const float* out_w   = (const float*)d_in[11];
    const float* out_b   = (const float*)d_in[12];
    const float* ln_w    = (const float*)d_in[13];
    const float* ln_b    = (const float*)d_in[14];
    const float* pos_w   = (const float*)d_in[15];
    const float* pos_b   = (const float*)d_in[16];
    float* out = (float*)d_out;

    cudaFuncSetAttribute(conv_mma_kernel,
                         cudaFuncAttributeMaxDynamicSharedMemorySize, MMA_SMEM);

    detect_kernel<<<1, 256>>>((const int*)src_mask);
    bias_kernel<<<(BB * MEM + 255) / 256, 256>>>(src_mask, notdone);
    wprep_kernel<<<2 * 4 * NCHUNK, 256>>>(main_w, proj_w);
    for (int n = 0; n < LNUM; n++) {
        int tot = BB * C_MAIN * PIX;
        prep_kernel<<<(tot + 255) / 256, 256>>>(x, h0, n, n == 0 ? 1 : 0);
        conv_mma_kernel<<<dim3(64, 4), 256, MMA_SMEM>>>(main_b, proj_b, n);
        attn_kernel<<<dim3(BB, NHH), 256>>>(k0, v0, pos_w, pos_b, n);
        final_kernel<<<BB, 256>>>(out_w, out_b, ln_w, ln_b, c0, x, n,
                                  out, n == LNUM - 1 ? 1 : 0);
    }
}

// round 10
// speedup vs baseline: 1.8428x; 1.2397x over previous
#include <cuda_runtime.h>
#include <cuda_bf16.h>
#include <cstdint>

// Problem constants
#define LNUM 2
#define BB   128
#define CIN  64
#define EE   64
#define NHH  8
#define MEM  40
#define HD   8
#define THD  512         // HD*HW
#define PIX  64          // spatial size
#define C_MAIN 192       // CIN + 2E
#define C_PROJ 128       // CIN + E
#define CO_MAIN 320      // 5E
#define CO_PROJ 192      // 3E

// ---- warp-MMA GEMM config ----
// Fused GEMM: M=512, N=8192 (128 b x 64 px), K=1728 (9 taps x 192 ch).
// Block: 256 thr (8 warps as 4m x 2n), tile M=128 x N=128, K chunk 64.
// Double-buffered smem; B gather register-prefetched.
#define NCHUNK 27
#define ASTR 72                 // padded bf16 row stride (36 words % 32 = 4)
#define SA_ELEMS (128 * ASTR)   // 9216 bf16 per tile
#define SA_BYTES (SA_ELEMS * 2) // 18432 B
#define MMA_SMEM (8 * SA_BYTES) // 147456 B (2 bufs x {Ah,Al,Bh,Bl})

// ---------------- scratch (device globals; no allocation) ----------------
__device__ unsigned g_ipk [BB * C_MAIN * PIX];  // packed bf16 (hi | lo<<16)
__device__ float g_gates[BB * CO_MAIN * PIX];   // (B,320,64)
__device__ float g_kqv  [BB * CO_PROJ * PIX];   // (B,192,64)
__device__ float g_attn [BB * EE * PIX];        // (B,64,64)
__device__ float g_out  [BB * EE * PIX];        // (B,64,64)
__device__ float g_bias [BB * MEM];
__device__ float g_nd   [BB];
__device__ int   g_is_i32;
// pre-split bf16 weight tiles, plain [128 r][64 k]: [layer][mtile][chunk]
__device__ __nv_bfloat16 g_wA_hi[2 * 4 * NCHUNK * 8192];
__device__ __nv_bfloat16 g_wA_lo[2 * 4 * NCHUNK * 8192];

__device__ __forceinline__ float sigmoidf_(float v) {
    return 1.0f / (1.0f + __expf(-v));
}

__device__ __forceinline__ uint32_t smem_to_u32(const void* p) {
    uint32_t a;
    asm("{ .reg .u64 t; cvta.to.shared.u64 t, %1; cvt.u32.u64 %0, t; }"
        : "=r"(a) : "l"(p));
    return a;
}
__device__ __forceinline__ void ldsm4(uint32_t addr, uint32_t* r) {
    asm volatile("ldmatrix.sync.aligned.m8n8.x4.shared.b16 {%0,%1,%2,%3}, [%4];"
        : "=r"(r[0]), "=r"(r[1]), "=r"(r[2]), "=r"(r[3]) : "r"(addr));
}
__device__ __forceinline__ void mma16816(float* d, const uint32_t* a,
                                         uint32_t b0, uint32_t b1) {
    asm volatile(
        "mma.sync.aligned.m16n8k16.row.col.f32.bf16.bf16.f32 "
        "{%0,%1,%2,%3}, {%4,%5,%6,%7}, {%8,%9}, {%0,%1,%2,%3};"
        : "+f"(d[0]), "+f"(d[1]), "+f"(d[2]), "+f"(d[3])
        : "r"(a[0]), "r"(a[1]), "r"(a[2]), "r"(a[3]), "r"(b0), "r"(b1));
}

// ---------------- dtype detection for bool inputs (parallel) ----------------
__global__ void detect_kernel(const int* __restrict__ sm) {
    __shared__ int bad;
    if (threadIdx.x == 0) bad = 0;
    __syncthreads();
    int anybad = 0;
    for (int i = threadIdx.x; i < (BB * MEM) / 4; i += 256) {
        int v = sm[i];
        if (v != 0 && v != 1) anybad = 1;
    }
    if (anybad) bad = 1;
    __syncthreads();
    if (threadIdx.x == 0) g_is_i32 = !bad;
}

__device__ __forceinline__ int read_bool(const void* p, int idx) {
    if (g_is_i32) return ((const int*)p)[idx] != 0;
    return ((const unsigned char*)p)[idx] != 0;
}

// ---------------- bias + notdone ----------------
__global__ void bias_kernel(const void* __restrict__ src_mask,
                            const void* __restrict__ notdone) {
    int t = blockIdx.x * 256 + threadIdx.x;
    if (t < BB) g_nd[t] = read_bool(notdone, t) ? 1.0f : 0.0f;
    if (t >= BB * MEM) return;
    int b = t / MEM, m = t - b * MEM;
    float v;
    if (m == MEM - 1) {
        v = 3.0f;  // MASK_B
    } else {
        bool masked = read_bool(src_mask, b * MEM + m + 1) || !read_bool(notdone, b);
        v = masked ? -1e9f : 0.0f;
    }
    g_bias[t] = v;
}

// ---------------- weight prepass: bf16 hi/lo split, plain tiles ----------
__global__ void wprep_kernel(const float* __restrict__ main_w,
                             const float* __restrict__ proj_w) {
    int id = blockIdx.x;
    int n = id / (4 * NCHUNK);
    int r2 = id % (4 * NCHUNK);
    int mtile = r2 / NCHUNK;
    int chunk = r2 % NCHUNK;
    int t  = chunk / 3;
    int c0 = (chunk % 3) * 64;
    __nv_bfloat16* dh = g_wA_hi + (size_t)id * 8192;
    __nv_bfloat16* dl = g_wA_lo + (size_t)id * 8192;
    for (int e = threadIdx.x; e < 8192; e += 256) {
        int r = e >> 6, kk = e & 63;
        int c = c0 + kk;
        int gco = mtile * 128 + r;
        float w = 0.0f;
        if (gco < CO_MAIN) {
            w = main_w[(((size_t)n * CO_MAIN + gco) * C_MAIN + c) * 9 + t];
        } else if (c < C_PROJ) {
            w = proj_w[(((size_t)n * CO_PROJ + (gco - CO_MAIN)) * C_PROJ + c) * 9 + t];
        }
        __nv_bfloat16 h = __float2bfloat16(w);
        __nv_bfloat16 l = __float2bfloat16(w - __bfloat162float(h));
        dh[e] = h;
        dl[e] = l;
    }
}

// ---------------- build concat input, packed bf16 hi/lo ----------------
__global__ void prep_kernel(const float* __restrict__ x,
                            const float* __restrict__ h0,
                            int n, int first) {
    int idx = blockIdx.x * 256 + threadIdx.x;
    if (idx >= BB * C_MAIN * PIX) return;
    int b = idx / (C_MAIN * PIX);
    int r = idx - b * (C_MAIN * PIX);
    int c = r >> 6;
    int p = r & 63;
    float nd = g_nd[b];
    float v;
    if (c < CIN) {
        v = x[b * (CIN * PIX) + r];
    } else if (c < CIN + EE) {
        int off = b * (EE * PIX) + (c - CIN) * PIX + p;
        if (first)
            v = h0[((size_t)(LNUM - 1) * BB + b) * (EE * PIX) + (c - CIN) * PIX + p] * nd;
        else
            v = g_out[off];
    } else {
        v = h0[((size_t)n * BB + b) * (EE * PIX) + (c - CIN - EE) * PIX + p] * nd;
    }
    __nv_bfloat16 h = __float2bfloat16(v);
    __nv_bfloat16 l = __float2bfloat16(v - __bfloat162float(h));
    g_ipk[idx] = (unsigned)__bfloat16_as_ushort(h)
               | ((unsigned)__bfloat16_as_ushort(l) << 16);
}

// ---------------- warp-MMA fused conv GEMM (double-buffered) -------------
__global__ void __launch_bounds__(256, 1)
conv_mma_kernel(const float* __restrict__ main_b,
                const float* __restrict__ proj_b,
                int n) {
    extern __shared__ __nv_bfloat16 smb[];
    uint32_t smb_u = smem_to_u32(smb);

    int tid = threadIdx.x;
    int lane = tid & 31, w = tid >> 5;
    int ntile = blockIdx.x, mtile = blockIdx.y;
    int b0 = ntile * 2;
    int mrow0 = (w >> 1) * 32;
    int nc0 = (w & 1) * 64;

    float acc[2][8][4];
#pragma unroll
    for (int mi = 0; mi < 2; mi++)
#pragma unroll
        for (int ni = 0; ni < 8; ni++)
#pragma unroll
            for (int j = 0; j < 4; j++) acc[mi][ni][j] = 0.0f;

    int lr = lane & 15, lc = lane >> 4;
    uint32_t aoff = (uint32_t)(((mrow0 + lr) * ASTR + lc * 8) * 2);
    uint32_t boff = (uint32_t)(((nc0 + lr) * ASTR + lc * 8) * 2);

    // B-staging geometry (thread -> one B row, 32 channels)
    int brow = tid >> 1, half = tid & 1;
    int bb = brow >> 6, px = brow & 63;
    int yy = px >> 3, xx = px & 7;

    unsigned regBh[16], regBl[16];

    // ---- register prefetch of B gather for a chunk ----
    auto loadB = [&](int chunk) {
        int t = chunk / 3, c0 = (chunk % 3) * 64;
        int ty = t / 3, tx = t % 3;
        int iy = yy + ty - 1, ix = xx + tx - 1;
        bool valid = ((unsigned)iy < 8u) && ((unsigned)ix < 8u);
        const unsigned* src = g_ipk
            + ((size_t)(b0 + bb) * C_MAIN + c0 + half * 32) * PIX
            + (valid ? iy * 8 + ix : 0);
#pragma unroll
        for (int j = 0; j < 16; j++) {
            unsigned u0 = valid ? src[(2 * j) * PIX] : 0u;
            unsigned u1 = valid ? src[(2 * j + 1) * PIX] : 0u;
            regBh[j] = __byte_perm(u0, u1, 0x5410);
            regBl[j] = __byte_perm(u0, u1, 0x7632);
        }
    };
    // ---- store staged B + copy A (global->smem) into a buffer ----
    auto storeChunk = [&](int chunk, int buf) {
        __nv_bfloat16* base = smb + (size_t)buf * 4 * SA_ELEMS;
        // A tiles (L2-hot, shared across all n-tiles)
        size_t toff = (((size_t)n * 4 + mtile) * NCHUNK + chunk) * 8192;
        const uint4* shh = (const uint4*)(g_wA_hi + toff);
        const uint4* sll = (const uint4*)(g_wA_lo + toff);
#pragma unroll
        for (int i = 0; i < 4; i++) {
            int e = tid + 256 * i;
            int r = e >> 3, c = e & 7;
            *(uint4*)&base[r * ASTR + c * 8] = shh[e];
            *(uint4*)&base[SA_ELEMS + r * ASTR + c * 8] = sll[e];
        }
        // B tiles from prefetched regs
        unsigned* bh = (unsigned*)(base + 2 * SA_ELEMS) + brow * (ASTR / 2) + half * 16;
        unsigned* bl = (unsigned*)(base + 3 * SA_ELEMS) + brow * (ASTR / 2) + half * 16;
#pragma unroll
        for (int j = 0; j < 16; j++) { bh[j] = regBh[j]; bl[j] = regBl[j]; }
    };

    loadB(0);
    storeChunk(0, 0);
    __syncthreads();

    for (int chunk = 0; chunk < NCHUNK; chunk++) {
        int buf = chunk & 1;
        if (chunk + 1 < NCHUNK) loadB(chunk + 1);

        uint32_t pbase = smb_u + (uint32_t)buf * 4 * SA_BYTES;
        uint32_t pAh = pbase, pAl = pbase + SA_BYTES;
        uint32_t pBh = pbase + 2 * SA_BYTES, pBl = pbase + 3 * SA_BYTES;
#pragma unroll
        for (int ks = 0; ks < 4; ks++) {
            uint32_t kb = (uint32_t)(ks * 32);
            uint32_t ah[2][4], al[2][4], bh[4][4], bl[4][4];
            ldsm4(pAh + aoff + kb, ah[0]);
            ldsm4(pAh + aoff + 16 * ASTR * 2 + kb, ah[1]);
            ldsm4(pAl + aoff + kb, al[0]);
            ldsm4(pAl + aoff + 16 * ASTR * 2 + kb, al[1]);
#pragma unroll
            for (int pn = 0; pn < 4; pn++) {
                ldsm4(pBh + boff + pn * 16 * ASTR * 2 + kb, bh[pn]);
                ldsm4(pBl + boff + pn * 16 * ASTR * 2 + kb, bl[pn]);
            }
#pragma unroll
            for (int mi = 0; mi < 2; mi++) {
#pragma unroll
                for (int ni = 0; ni < 8; ni++) {
                    int pn = ni >> 1, o = ni & 1;
                    mma16816(acc[mi][ni], ah[mi], bh[pn][o], bh[pn][o + 2]);
                    mma16816(acc[mi][ni], ah[mi], bl[pn][o], bl[pn][o + 2]);
                    mma16816(acc[mi][ni], al[mi], bh[pn][o], bh[pn][o + 2]);
                }
            }
        }
        if (chunk + 1 < NCHUNK) {
            storeChunk(chunk + 1, 1 - buf);
            __syncthreads();
        }
    }

    // ---- epilogue: bias add + direct stores ----
    int batch = b0 + (w & 1);
#pragma unroll
    for (int mi = 0; mi < 2; mi++) {
#pragma unroll
        for (int rr = 0; rr < 2; rr++) {
            int r = mrow0 + mi * 16 + rr * 8 + (lane >> 2);
            int gr = mtile * 128 + r;
            bool ismain = (gr < CO_MAIN);
            float bias = ismain ? main_b[n * CO_MAIN + gr]
                                : proj_b[n * CO_PROJ + (gr - CO_MAIN)];
            float* dst = ismain
                ? g_gates + ((size_t)batch * CO_MAIN + gr) * PIX
                : g_kqv  + ((size_t)batch * CO_PROJ + (gr - CO_MAIN)) * PIX;
#pragma unroll
            for (int ni = 0; ni < 8; ni++) {
                int pxc = ni * 8 + (lane & 3) * 2;
                float2 v;
                v.x = acc[mi][ni][rr * 2 + 0] + bias;
                v.y = acc[mi][ni][rr * 2 + 1] + bias;
                *(float2*)&dst[pxc] = v;
            }
        }
    }
}

// ---------------- attention over rolling memory ----------------
__global__ void attn_kernel(const float* __restrict__ k0,
                            const float* __restrict__ v0,
                            const float* __restrict__ pos_w,
                            const float* __restrict__ pos_b,
                            int n) {
    int b = blockIdx.x;
    int h = blockIdx.y;
    int tid = threadIdx.x;
    __shared__ float q[THD], kn[THD], vn[THD];
    __shared__ float sc[MEM], wts[MEM];

    const float* kqv = g_kqv + (size_t)b * CO_PROJ * PIX;
    const float rscale = 0.044194173824159216f;  // 1/sqrt(512)
    for (int d = tid; d < THD; d += 256) {
        int hd = d >> 6, hw = d & 63;
        kn[d] = kqv[(h * 24 + hd) * PIX + hw];
        q[d]  = kqv[(h * 24 + 8 + hd) * PIX + hw] * rscale;
        vn[d] = kqv[(h * 24 + 16 + hd) * PIX + hw];
    }
    __syncthreads();

    const float* kb  = k0 + ((((size_t)n * BB + b) * NHH + h) * MEM) * THD;
    const float* pwb = pos_w + (size_t)n * MEM * (NHH * THD) + h * THD;
    int warp = tid >> 5, lane = tid & 31;
    for (int m = warp; m < MEM; m += 8) {
        const float* kr = (m < MEM - 1) ? (kb + (size_t)(m + 1) * THD) : kn;
        const float* pr = pwb + (size_t)m * (NHH * THD);
        float p = 0.0f;
        for (int d = lane; d < THD; d += 32)
            p = fmaf(q[d], kr[d] + pr[d], p);
#pragma unroll
        for (int o = 16; o; o >>= 1) p += __shfl_xor_sync(0xffffffffu, p, o);
        if (lane == 0)
            sc[m] = p + g_bias[b * MEM + m] + pos_b[(size_t)n * MEM * NHH + m * NHH + h];
    }
    __syncthreads();
    if (tid == 0) {
        float mx = sc[0];
#pragma unroll
        for (int m = 1; m < MEM; m++) mx = fmaxf(mx, sc[m]);
        float s = 0.0f;
#pragma unroll
        for (int m = 0; m < MEM; m++) {
            float e = __expf(sc[m] - mx);
            wts[m] = e;
            s += e;
        }
        float inv = 1.0f / s;
#pragma unroll
        for (int m = 0; m < MEM; m++) wts[m] *= inv;
    }
    __syncthreads();

    const float* vb = v0 + ((((size_t)n * BB + b) * NHH + h) * MEM) * THD;
    for (int d = tid; d < THD; d += 256) {
        float acc = wts[MEM - 1] * vn[d];
        for (int m = 0; m < MEM - 1; m++)
            acc = fmaf(wts[m], vb[(size_t)(m + 1) * THD + d], acc);
        int hd = d >> 6, hw = d & 63;
        g_attn[(size_t)b * (EE * PIX) + (h * 8 + hd) * PIX + hw] = acc;
    }
}

// ---------------- out conv + residual + layernorm + LSTM combine ---------
__global__ void final_kernel(const float* __restrict__ out_w,
                             const float* __restrict__ out_b,
                             const float* __restrict__ ln_w,
                             const float* __restrict__ ln_b,
                             const float* __restrict__ c0,
                             const float* __restrict__ x,
                             int n, float* __restrict__ dst_last, int last) {
    __shared__ float sa[EE * 100];   // padded attn input
    __shared__ float ao[EE * PIX];   // conv+residual result
    __shared__ float red[16];
    __shared__ float s_mu, s_rv;
    int b = blockIdx.x;
    int tid = threadIdx.x;

    for (int i = tid; i < EE * 100; i += 256) sa[i] = 0.0f;
    __syncthreads();
    const float* at = g_attn + (size_t)b * EE * PIX;
    for (int i = tid; i < EE * PIX; i += 256) {
        int c = i >> 6, p = i & 63;
        sa[c * 100 + ((p >> 3) + 1) * 10 + (p & 7) + 1] = at[i];
    }
    __syncthreads();

    const float* wb = out_w + (size_t)n * EE * EE * 9;
    const float* xr = x + (size_t)b * EE * PIX;
    for (int t = tid; t < EE * 8; t += 256) {
        int co = t >> 3;
        int row = t & 7;
        const float* wc = wb + (size_t)co * EE * 9;
        float acc[8];
#pragma unroll
        for (int xx = 0; xx < 8; xx++) acc[xx] = 0.0f;
        for (int c = 0; c < EE; c++) {
            const float* s = sa + c * 100 + row * 10;
            const float* w = wc + c * 9;
            float w0 = w[0], w1 = w[1], w2 = w[2];
            float w3 = w[3], w4 = w[4], w5 = w[5];
            float w6 = w[6], w7 = w[7], w8 = w[8];
#pragma unroll
            for (int xx = 0; xx < 8; xx++) {
                float a = acc[xx];
                a = fmaf(s[xx],      w0, a);
                a = fmaf(s[xx + 1],  w1, a);
                a = fmaf(s[xx + 2],  w2, a);
                a = fmaf(s[10 + xx],     w3, a);
                a = fmaf(s[10 + xx + 1], w4, a);
                a = fmaf(s[10 + xx + 2], w5, a);
                a = fmaf(s[20 + xx],     w6, a);
                a = fmaf(s[20 + xx + 1], w7, a);
                a = fmaf(s[20 + xx + 2], w8, a);
                acc[xx] = a;
            }
        }
        float bb = out_b[n * EE + co];
        int base = co * PIX + row * 8;
#pragma unroll
        for (int xx = 0; xx < 8; xx++)
            ao[base + xx] = acc[xx] + bb + xr[base + xx];
    }
    __syncthreads();

    float s1 = 0.0f, s2 = 0.0f;
    for (int i = tid; i < EE * PIX; i += 256) {
        float v = ao[i];
        s1 += v;
        s2 += v * v;
    }
    int warp = tid >> 5, lane = tid & 31;
#pragma unroll
    for (int o = 16; o; o >>= 1) {
        s1 += __shfl_xor_sync(0xffffffffu, s1, o);
        s2 += __shfl_xor_sync(0xffffffffu, s2, o);
    }
    if (lane == 0) { red[warp] = s1; red[8 + warp] = s2; }
    __syncthreads();
    if (tid == 0) {
        float a = 0.0f, q2 = 0.0f;
#pragma unroll
        for (int w2 = 0; w2 < 8; w2++) { a += red[w2]; q2 += red[8 + w2]; }
        float mu = a * (1.0f / 4096.0f);
        float var = q2 * (1.0f / 4096.0f) - mu * mu;
        s_mu = mu;
        s_rv = rsqrtf(var + 1e-5f);
    }
    __syncthreads();
    float mu = s_mu, rv = s_rv;

    const float* gb = g_gates + (size_t)b * CO_MAIN * PIX;
    const float* cb = c0 + ((size_t)n * BB + b) * (EE * PIX);
    float nd = g_nd[b];
    float* dst = (last ? dst_last : g_out) + (size_t)b * EE * PIX;
    const float* lw = ln_w + (size_t)n * EE * PIX;
    const float* lb = ln_b + (size_t)n * EE * PIX;
    for (int i = tid; i < EE * PIX; i += 256) {
        int c = i >> 6, p = i & 63;
        float aon = (ao[i] - mu) * rv * lw[i] + lb[i];
        float gi = sigmoidf_(gb[(0 * EE + c) * PIX + p]);
        float gf = sigmoidf_(gb[(1 * EE + c) * PIX + p]);
        float go = sigmoidf_(gb[(2 * EE + c) * PIX + p]);
        float gg = tanhf(gb[(3 * EE + c) * PIX + p]);
        float ga = sigmoidf_(gb[(4 * EE + c) * PIX + p]);
        float cn = gf * (cb[i] * nd) + gi * gg + ga * tanhf(aon);
        dst[i] = go * tanhf(cn);
    }
}

// ---------------- launch ----------------
extern "C" void kernel_launch(void* const* d_in, const int* in_sizes, int n_in,
                              void* d_out, int out_size) {
    const float* x       = (const float*)d_in[0];
    const float* h0      = (const float*)d_in[1];
    const float* c0      = (const float*)d_in[2];
    const float* k0      = (const float*)d_in[3];
    const float* v0      = (const float*)d_in[4];
    const void*  src_mask = d_in[5];
    const void*  notdone  = d_in[6];
    const float* main_w  = (const float*)d_in[7];
    const float* main_b  = (const float*)d_in[8];
    const float* proj_w  = (const float*)d_in[9];
    const float* proj_b  = (const float*)d_in[10];
    const float* out_w   = (const float*)d_in[11];
    const float* out_b   = (const float*)d_in[12];
    const float* ln_w    = (const float*)d_in[13];
    const float* ln_b    = (const float*)d_in[14];
    const float* pos_w   = (const float*)d_in[15];
    const float* pos_b   = (const float*)d_in[16];
    float* out = (float*)d_out;

    cudaFuncSetAttribute(conv_mma_kernel,
                         cudaFuncAttributeMaxDynamicSharedMemorySize, MMA_SMEM);

    detect_kernel<<<1, 256>>>((const int*)src_mask);
    bias_kernel<<<(BB * MEM + 255) / 256, 256>>>(src_mask, notdone);
    wprep_kernel<<<2 * 4 * NCHUNK, 256>>>(main_w, proj_w);
    for (int n = 0; n < LNUM; n++) {
        int tot = BB * C_MAIN * PIX;
        prep_kernel<<<(tot + 255) / 256, 256>>>(x, h0, n, n == 0 ? 1 : 0);
        conv_mma_kernel<<<dim3(64, 4), 256, MMA_SMEM>>>(main_b, proj_b, n);
        attn_kernel<<<dim3(BB, NHH), 256>>>(k0, v0, pos_w, pos_b, n);
        final_kernel<<<BB, 256>>>(out_w, out_b, ln_w, ln_b, c0, x, n,
                                  out, n == LNUM - 1 ? 1 : 0);
    }
}

// round 11
// speedup vs baseline: 1.9418x; 1.0537x over previous
#include <cuda_runtime.h>
#include <cuda_bf16.h>
#include <cstdint>

// Problem constants
#define LNUM 2
#define BB   128
#define CIN  64
#define EE   64
#define NHH  8
#define MEM  40
#define HD   8
#define THD  512         // HD*HW
#define PIX  64          // spatial size
#define C_MAIN 192       // CIN + 2E
#define C_PROJ 128       // CIN + E
#define CO_MAIN 320      // 5E
#define CO_PROJ 192      // 3E

// ---- warp-MMA GEMM config ----
// Fused GEMM: M=512, N=8192 (128 b x 64 px), K=1728 (9 taps x 192 ch).
// Block: 256 thr (8 warps as 4m x 2n), tile M=128 x N=128, K chunk 32.
// Double-buffered smem (2 blocks/SM); A via cp.async, B reg-prefetched.
#define NCHUNK 54               // 9 taps * 6 channel-blocks of 32
#define ASTR 40                 // padded bf16 row stride (20 words % 32 = 20)
#define TILE_ELEMS (128 * ASTR) // 5120 bf16 per tile
#define TILE_BYTES (TILE_ELEMS * 2)  // 10240 B
#define MMA_SMEM (8 * TILE_BYTES)    // 81920 B (2 bufs x {Ah,Al,Bh,Bl})

// ---------------- scratch (device globals; no allocation) ----------------
__device__ unsigned g_ipk [BB * C_MAIN * PIX];  // packed bf16 (hi | lo<<16)
__device__ float g_gates[BB * CO_MAIN * PIX];   // (B,320,64)
__device__ float g_kqv  [BB * CO_PROJ * PIX];   // (B,192,64)
__device__ float g_attn [BB * EE * PIX];        // (B,64,64)
__device__ float g_out  [BB * EE * PIX];        // (B,64,64)
__device__ float g_bias [BB * MEM];
__device__ float g_nd   [BB];
__device__ int   g_is_i32;
// pre-split bf16 weight tiles, plain [128 r][32 k]: [layer][mtile][chunk]
__device__ __nv_bfloat16 g_wA_hi[2 * 4 * NCHUNK * 4096];
__device__ __nv_bfloat16 g_wA_lo[2 * 4 * NCHUNK * 4096];

__device__ __forceinline__ float sigmoidf_(float v) {
    return 1.0f / (1.0f + __expf(-v));
}

__device__ __forceinline__ uint32_t smem_to_u32(const void* p) {
    uint32_t a;
    asm("{ .reg .u64 t; cvta.to.shared.u64 t, %1; cvt.u32.u64 %0, t; }"
        : "=r"(a) : "l"(p));
    return a;
}
__device__ __forceinline__ void ldsm4(uint32_t addr, uint32_t* r) {
    asm volatile("ldmatrix.sync.aligned.m8n8.x4.shared.b16 {%0,%1,%2,%3}, [%4];"
        : "=r"(r[0]), "=r"(r[1]), "=r"(r[2]), "=r"(r[3]) : "r"(addr));
}
__device__ __forceinline__ void mma16816(float* d, const uint32_t* a,
                                         uint32_t b0, uint32_t b1) {
    asm volatile(
        "mma.sync.aligned.m16n8k16.row.col.f32.bf16.bf16.f32 "
        "{%0,%1,%2,%3}, {%4,%5,%6,%7}, {%8,%9}, {%0,%1,%2,%3};"
        : "+f"(d[0]), "+f"(d[1]), "+f"(d[2]), "+f"(d[3])
        : "r"(a[0]), "r"(a[1]), "r"(a[2]), "r"(a[3]), "r"(b0), "r"(b1));
}
__device__ __forceinline__ void cpasync16(uint32_t dst, const void* src) {
    asm volatile("cp.async.cg.shared.global [%0], [%1], 16;"
                 :: "r"(dst), "l"(src) : "memory");
}
__device__ __forceinline__ void cpasync_commit() {
    asm volatile("cp.async.commit_group;" ::: "memory");
}
__device__ __forceinline__ void cpasync_wait0() {
    asm volatile("cp.async.wait_group 0;" ::: "memory");
}

// ---------------- dtype detection for bool inputs (parallel) ----------------
__global__ void detect_kernel(const int* __restrict__ sm) {
    __shared__ int bad;
    if (threadIdx.x == 0) bad = 0;
    __syncthreads();
    int anybad = 0;
    for (int i = threadIdx.x; i < (BB * MEM) / 4; i += 256) {
        int v = sm[i];
        if (v != 0 && v != 1) anybad = 1;
    }
    if (anybad) bad = 1;
    __syncthreads();
    if (threadIdx.x == 0) g_is_i32 = !bad;
}

__device__ __forceinline__ int read_bool(const void* p, int idx) {
    if (g_is_i32) return ((const int*)p)[idx] != 0;
    return ((const unsigned char*)p)[idx] != 0;
}

// ---------------- bias + notdone ----------------
__global__ void bias_kernel(const void* __restrict__ src_mask,
                            const void* __restrict__ notdone) {
    int t = blockIdx.x * 256 + threadIdx.x;
    if (t < BB) g_nd[t] = read_bool(notdone, t) ? 1.0f : 0.0f;
    if (t >= BB * MEM) return;
    int b = t / MEM, m = t - b * MEM;
    float v;
    if (m == MEM - 1) {
        v = 3.0f;  // MASK_B
    } else {
        bool masked = read_bool(src_mask, b * MEM + m + 1) || !read_bool(notdone, b);
        v = masked ? -1e9f : 0.0f;
    }
    g_bias[t] = v;
}

// ---------------- weight prepass: bf16 hi/lo split, [128 x 32] tiles ------
__global__ void wprep_kernel(const float* __restrict__ main_w,
                             const float* __restrict__ proj_w) {
    int id = blockIdx.x;
    int n = id / (4 * NCHUNK);
    int r2 = id % (4 * NCHUNK);
    int mtile = r2 / NCHUNK;
    int chunk = r2 % NCHUNK;
    int t  = chunk / 6;
    int c0 = (chunk % 6) * 32;
    __nv_bfloat16* dh = g_wA_hi + (size_t)id * 4096;
    __nv_bfloat16* dl = g_wA_lo + (size_t)id * 4096;
    for (int e = threadIdx.x; e < 4096; e += 256) {
        int r = e >> 5, kk = e & 31;
        int c = c0 + kk;
        int gco = mtile * 128 + r;
        float w = 0.0f;
        if (gco < CO_MAIN) {
            w = main_w[(((size_t)n * CO_MAIN + gco) * C_MAIN + c) * 9 + t];
        } else if (c < C_PROJ) {
            w = proj_w[(((size_t)n * CO_PROJ + (gco - CO_MAIN)) * C_PROJ + c) * 9 + t];
        }
        __nv_bfloat16 h = __float2bfloat16(w);
        __nv_bfloat16 l = __float2bfloat16(w - __bfloat162float(h));
        dh[e] = h;
        dl[e] = l;
    }
}

// ---------------- build concat input, packed bf16 hi/lo ----------------
__global__ void prep_kernel(const float* __restrict__ x,
                            const float* __restrict__ h0,
                            int n, int first) {
    int idx = blockIdx.x * 256 + threadIdx.x;
    if (idx >= BB * C_MAIN * PIX) return;
    int b = idx / (C_MAIN * PIX);
    int r = idx - b * (C_MAIN * PIX);
    int c = r >> 6;
    int p = r & 63;
    float nd = g_nd[b];
    float v;
    if (c < CIN) {
        v = x[b * (CIN * PIX) + r];
    } else if (c < CIN + EE) {
        int off = b * (EE * PIX) + (c - CIN) * PIX + p;
        if (first)
            v = h0[((size_t)(LNUM - 1) * BB + b) * (EE * PIX) + (c - CIN) * PIX + p] * nd;
        else
            v = g_out[off];
    } else {
        v = h0[((size_t)n * BB + b) * (EE * PIX) + (c - CIN - EE) * PIX + p] * nd;
    }
    __nv_bfloat16 h = __float2bfloat16(v);
    __nv_bfloat16 l = __float2bfloat16(v - __bfloat162float(h));
    g_ipk[idx] = (unsigned)__bfloat16_as_ushort(h)
               | ((unsigned)__bfloat16_as_ushort(l) << 16);
}

// ---------------- warp-MMA fused conv GEMM (K=32, 2 blocks/SM) -----------
__global__ void __launch_bounds__(256, 2)
conv_mma_kernel(const float* __restrict__ main_b,
                const float* __restrict__ proj_b,
                int n) {
    extern __shared__ __nv_bfloat16 smb[];
    uint32_t smb_u = smem_to_u32(smb);

    int tid = threadIdx.x;
    int lane = tid & 31, w = tid >> 5;
    int ntile = blockIdx.x, mtile = blockIdx.y;
    int b0 = ntile * 2;
    int mrow0 = (w >> 1) * 32;
    int nc0 = (w & 1) * 64;

    float acc[2][8][4];
#pragma unroll
    for (int mi = 0; mi < 2; mi++)
#pragma unroll
        for (int ni = 0; ni < 8; ni++)
#pragma unroll
            for (int j = 0; j < 4; j++) acc[mi][ni][j] = 0.0f;

    int lr = lane & 15, lc = lane >> 4;
    uint32_t aoff = (uint32_t)(((mrow0 + lr) * ASTR + lc * 8) * 2);
    uint32_t boff = (uint32_t)(((nc0 + lr) * ASTR + lc * 8) * 2);

    // B-staging geometry (thread -> one B row half: 16 channels)
    int brow = tid >> 1, half = tid & 1;
    int bb = brow >> 6, px = brow & 63;
    int yy = px >> 3, xx = px & 7;

    unsigned regBh[8], regBl[8];

    // ---- register prefetch of B gather for a chunk ----
    auto loadB = [&](int chunk) {
        int t = chunk / 6, c0 = (chunk % 6) * 32;
        int ty = t / 3, tx = t % 3;
        int iy = yy + ty - 1, ix = xx + tx - 1;
        bool valid = ((unsigned)iy < 8u) && ((unsigned)ix < 8u);
        const unsigned* src = g_ipk
            + ((size_t)(b0 + bb) * C_MAIN + c0 + half * 16) * PIX
            + (valid ? iy * 8 + ix : 0);
#pragma unroll
        for (int j = 0; j < 8; j++) {
            unsigned u0 = valid ? src[(2 * j) * PIX] : 0u;
            unsigned u1 = valid ? src[(2 * j + 1) * PIX] : 0u;
            regBh[j] = __byte_perm(u0, u1, 0x5410);
            regBl[j] = __byte_perm(u0, u1, 0x7632);
        }
    };
    // ---- async A tile copy (global -> smem, padded rows) ----
    auto issueA = [&](int chunk, int buf) {
        size_t toff = (((size_t)n * 4 + mtile) * NCHUNK + chunk) * 4096;
        const char* gh = (const char*)(g_wA_hi + toff);
        const char* gl = (const char*)(g_wA_lo + toff);
        uint32_t base = smb_u + (uint32_t)buf * 4 * TILE_BYTES;
#pragma unroll
        for (int i = 0; i < 2; i++) {
            int e = tid + 256 * i;          // 512 16B chunks per tile
            int row = e >> 2, c16 = e & 3;
            uint32_t d = base + row * (ASTR * 2) + c16 * 16;
            cpasync16(d, gh + e * 16);
            cpasync16(d + TILE_BYTES, gl + e * 16);
        }
        cpasync_commit();
    };
    // ---- store prefetched B regs into a buffer ----
    auto storeB = [&](int buf) {
        __nv_bfloat16* base = smb + (size_t)buf * 4 * TILE_ELEMS;
        unsigned* bh = (unsigned*)(base + 2 * TILE_ELEMS) + brow * (ASTR / 2) + half * 8;
        unsigned* bl = (unsigned*)(base + 3 * TILE_ELEMS) + brow * (ASTR / 2) + half * 8;
#pragma unroll
        for (int j = 0; j < 8; j++) { bh[j] = regBh[j]; bl[j] = regBl[j]; }
    };

    issueA(0, 0);
    loadB(0);
    storeB(0);
    cpasync_wait0();
    __syncthreads();

    for (int chunk = 0; chunk < NCHUNK; chunk++) {
        int buf = chunk & 1;
        if (chunk + 1 < NCHUNK) {
            issueA(chunk + 1, 1 - buf);
            loadB(chunk + 1);
        }

        uint32_t pbase = smb_u + (uint32_t)buf * 4 * TILE_BYTES;
        uint32_t pAh = pbase, pAl = pbase + TILE_BYTES;
        uint32_t pBh = pbase + 2 * TILE_BYTES, pBl = pbase + 3 * TILE_BYTES;
#pragma unroll
        for (int ks = 0; ks < 2; ks++) {
            uint32_t kb = (uint32_t)(ks * 32);
            uint32_t ah[2][4], al[2][4], bh[4][4], bl[4][4];
            ldsm4(pAh + aoff + kb, ah[0]);
            ldsm4(pAh + aoff + 16 * ASTR * 2 + kb, ah[1]);
            ldsm4(pAl + aoff + kb, al[0]);
            ldsm4(pAl + aoff + 16 * ASTR * 2 + kb, al[1]);
#pragma unroll
            for (int pn = 0; pn < 4; pn++) {
                ldsm4(pBh + boff + pn * 16 * ASTR * 2 + kb, bh[pn]);
                ldsm4(pBl + boff + pn * 16 * ASTR * 2 + kb, bl[pn]);
            }
#pragma unroll
            for (int mi = 0; mi < 2; mi++) {
#pragma unroll
                for (int ni = 0; ni < 8; ni++) {
                    int pn = ni >> 1, o = ni & 1;
                    mma16816(acc[mi][ni], ah[mi], bh[pn][o], bh[pn][o + 2]);
                    mma16816(acc[mi][ni], ah[mi], bl[pn][o], bl[pn][o + 2]);
                    mma16816(acc[mi][ni], al[mi], bh[pn][o], bh[pn][o + 2]);
                }
            }
        }
        if (chunk + 1 < NCHUNK) {
            storeB(1 - buf);
            cpasync_wait0();
            __syncthreads();
        }
    }

    // ---- epilogue: bias add + direct stores ----
    int batch = b0 + (w & 1);
#pragma unroll
    for (int mi = 0; mi < 2; mi++) {
#pragma unroll
        for (int rr = 0; rr < 2; rr++) {
            int r = mrow0 + mi * 16 + rr * 8 + (lane >> 2);
            int gr = mtile * 128 + r;
            bool ismain = (gr < CO_MAIN);
            float bias = ismain ? main_b[n * CO_MAIN + gr]
                                : proj_b[n * CO_PROJ + (gr - CO_MAIN)];
            float* dst = ismain
                ? g_gates + ((size_t)batch * CO_MAIN + gr) * PIX
                : g_kqv  + ((size_t)batch * CO_PROJ + (gr - CO_MAIN)) * PIX;
#pragma unroll
            for (int ni = 0; ni < 8; ni++) {
                int pxc = ni * 8 + (lane & 3) * 2;
                float2 v;
                v.x = acc[mi][ni][rr * 2 + 0] + bias;
                v.y = acc[mi][ni][rr * 2 + 1] + bias;
                *(float2*)&dst[pxc] = v;
            }
        }
    }
}

// ---------------- attention over rolling memory ----------------
__global__ void attn_kernel(const float* __restrict__ k0,
                            const float* __restrict__ v0,
                            const float* __restrict__ pos_w,
                            const float* __restrict__ pos_b,
                            int n) {
    int b = blockIdx.x;
    int h = blockIdx.y;
    int tid = threadIdx.x;
    __shared__ float q[THD], kn[THD], vn[THD];
    __shared__ float sc[MEM], wts[MEM];

    const float* kqv = g_kqv + (size_t)b * CO_PROJ * PIX;
    const float rscale = 0.044194173824159216f;  // 1/sqrt(512)
    for (int d = tid; d < THD; d += 256) {
        int hd = d >> 6, hw = d & 63;
        kn[d] = kqv[(h * 24 + hd) * PIX + hw];
        q[d]  = kqv[(h * 24 + 8 + hd) * PIX + hw] * rscale;
        vn[d] = kqv[(h * 24 + 16 + hd) * PIX + hw];
    }
    __syncthreads();

    const float* kb  = k0 + ((((size_t)n * BB + b) * NHH + h) * MEM) * THD;
    const float* pwb = pos_w + (size_t)n * MEM * (NHH * THD) + h * THD;
    int warp = tid >> 5, lane = tid & 31;
    for (int m = warp; m < MEM; m += 8) {
        const float* kr = (m < MEM - 1) ? (kb + (size_t)(m + 1) * THD) : kn;
        const float* pr = pwb + (size_t)m * (NHH * THD);
        float p = 0.0f;
        for (int d = lane; d < THD; d += 32)
            p = fmaf(q[d], kr[d] + pr[d], p);
#pragma unroll
        for (int o = 16; o; o >>= 1) p += __shfl_xor_sync(0xffffffffu, p, o);
        if (lane == 0)
            sc[m] = p + g_bias[b * MEM + m] + pos_b[(size_t)n * MEM * NHH + m * NHH + h];
    }
    __syncthreads();
    if (tid == 0) {
        float mx = sc[0];
#pragma unroll
        for (int m = 1; m < MEM; m++) mx = fmaxf(mx, sc[m]);
        float s = 0.0f;
#pragma unroll
        for (int m = 0; m < MEM; m++) {
            float e = __expf(sc[m] - mx);
            wts[m] = e;
            s += e;
        }
        float inv = 1.0f / s;
#pragma unroll
        for (int m = 0; m < MEM; m++) wts[m] *= inv;
    }
    __syncthreads();

    const float* vb = v0 + ((((size_t)n * BB + b) * NHH + h) * MEM) * THD;
    for (int d = tid; d < THD; d += 256) {
        float acc = wts[MEM - 1] * vn[d];
        for (int m = 0; m < MEM - 1; m++)
            acc = fmaf(wts[m], vb[(size_t)(m + 1) * THD + d], acc);
        int hd = d >> 6, hw = d & 63;
        g_attn[(size_t)b * (EE * PIX) + (h * 8 + hd) * PIX + hw] = acc;
    }
}

// ---------------- out conv + residual + layernorm + LSTM combine ---------
__global__ void final_kernel(const float* __restrict__ out_w,
                             const float* __restrict__ out_b,
                             const float* __restrict__ ln_w,
                             const float* __restrict__ ln_b,
                             const float* __restrict__ c0,
                             const float* __restrict__ x,
                             int n, float* __restrict__ dst_last, int last) {
    __shared__ float sa[EE * 100];   // padded attn input
    __shared__ float ao[EE * PIX];   // conv+residual result
    __shared__ float red[16];
    __shared__ float s_mu, s_rv;
    int b = blockIdx.x;
    int tid = threadIdx.x;

    for (int i = tid; i < EE * 100; i += 256) sa[i] = 0.0f;
    __syncthreads();
    const float* at = g_attn + (size_t)b * EE * PIX;
    for (int i = tid; i < EE * PIX; i += 256) {
        int c = i >> 6, p = i & 63;
        sa[c * 100 + ((p >> 3) + 1) * 10 + (p & 7) + 1] = at[i];
    }
    __syncthreads();

    const float* wb = out_w + (size_t)n * EE * EE * 9;
    const float* xr = x + (size_t)b * EE * PIX;
    for (int t = tid; t < EE * 8; t += 256) {
        int co = t >> 3;
        int row = t & 7;
        const float* wc = wb + (size_t)co * EE * 9;
        float acc[8];
#pragma unroll
        for (int xx = 0; xx < 8; xx++) acc[xx] = 0.0f;
        for (int c = 0; c < EE; c++) {
            const float* s = sa + c * 100 + row * 10;
            const float* w = wc + c * 9;
            float w0 = w[0], w1 = w[1], w2 = w[2];
            float w3 = w[3], w4 = w[4], w5 = w[5];
            float w6 = w[6], w7 = w[7], w8 = w[8];
#pragma unroll
            for (int xx = 0; xx < 8; xx++) {
                float a = acc[xx];
                a = fmaf(s[xx],      w0, a);
                a = fmaf(s[xx + 1],  w1, a);
                a = fmaf(s[xx + 2],  w2, a);
                a = fmaf(s[10 + xx],     w3, a);
                a = fmaf(s[10 + xx + 1], w4, a);
                a = fmaf(s[10 + xx + 2], w5, a);
                a = fmaf(s[20 + xx],     w6, a);
                a = fmaf(s[20 + xx + 1], w7, a);
                a = fmaf(s[20 + xx + 2], w8, a);
                acc[xx] = a;
            }
        }
        float bb = out_b[n * EE + co];
        int base = co * PIX + row * 8;
#pragma unroll
        for (int xx = 0; xx < 8; xx++)
            ao[base + xx] = acc[xx] + bb + xr[base + xx];
    }
    __syncthreads();

    float s1 = 0.0f, s2 = 0.0f;
    for (int i = tid; i < EE * PIX; i += 256) {
        float v = ao[i];
        s1 += v;
        s2 += v * v;
    }
    int warp = tid >> 5, lane = tid & 31;
#pragma unroll
    for (int o = 16; o; o >>= 1) {
        s1 += __shfl_xor_sync(0xffffffffu, s1, o);
        s2 += __shfl_xor_sync(0xffffffffu, s2, o);
    }
    if (lane == 0) { red[warp] = s1; red[8 + warp] = s2; }
    __syncthreads();
    if (tid == 0) {
        float a = 0.0f, q2 = 0.0f;
#pragma unroll
        for (int w2 = 0; w2 < 8; w2++) { a += red[w2]; q2 += red[8 + w2]; }
        float mu = a * (1.0f / 4096.0f);
        float var = q2 * (1.0f / 4096.0f) - mu * mu;
        s_mu = mu;
        s_rv = rsqrtf(var + 1e-5f);
    }
    __syncthreads();
    float mu = s_mu, rv = s_rv;

    const float* gb = g_gates + (size_t)b * CO_MAIN * PIX;
    const float* cb = c0 + ((size_t)n * BB + b) * (EE * PIX);
    float nd = g_nd[b];
    float* dst = (last ? dst_last : g_out) + (size_t)b * EE * PIX;
    const float* lw = ln_w + (size_t)n * EE * PIX;
    const float* lb = ln_b + (size_t)n * EE * PIX;
    for (int i = tid; i < EE * PIX; i += 256) {
        int c = i >> 6, p = i & 63;
        float aon = (ao[i] - mu) * rv * lw[i] + lb[i];
        float gi = sigmoidf_(gb[(0 * EE + c) * PIX + p]);
        float gf = sigmoidf_(gb[(1 * EE + c) * PIX + p]);
        float go = sigmoidf_(gb[(2 * EE + c) * PIX + p]);
        float gg = tanhf(gb[(3 * EE + c) * PIX + p]);
        float ga = sigmoidf_(gb[(4 * EE + c) * PIX + p]);
        float cn = gf * (cb[i] * nd) + gi * gg + ga * tanhf(aon);
        dst[i] = go * tanhf(cn);
    }
}

// ---------------- launch ----------------
extern "C" void kernel_launch(void* const* d_in, const int* in_sizes, int n_in,
                              void* d_out, int out_size) {
    const float* x       = (const float*)d_in[0];
    const float* h0      = (const float*)d_in[1];
    const float* c0      = (const float*)d_in[2];
    const float* k0      = (const float*)d_in[3];
    const float* v0      = (const float*)d_in[4];
    const void*  src_mask = d_in[5];
    const void*  notdone  = d_in[6];
    const float* main_w  = (const float*)d_in[7];
    const float* main_b  = (const float*)d_in[8];
    const float* proj_w  = (const float*)d_in[9];
    const float* proj_b  = (const float*)d_in[10];
    const float* out_w   = (const float*)d_in[11];
    const float* out_b   = (const float*)d_in[12];
    const float* ln_w    = (const float*)d_in[13];
    const float* ln_b    = (const float*)d_in[14];
    const float* pos_w   = (const float*)d_in[15];
    const float* pos_b   = (const float*)d_in[16];
    float* out = (float*)d_out;

    cudaFuncSetAttribute(conv_mma_kernel,
                         cudaFuncAttributeMaxDynamicSharedMemorySize, MMA_SMEM);

    detect_kernel<<<1, 256>>>((const int*)src_mask);
    bias_kernel<<<(BB * MEM + 255) / 256, 256>>>(src_mask, notdone);
    wprep_kernel<<<2 * 4 * NCHUNK, 256>>>(main_w, proj_w);
    for (int n = 0; n < LNUM; n++) {
        int tot = BB * C_MAIN * PIX;
        prep_kernel<<<(tot + 255) / 256, 256>>>(x, h0, n, n == 0 ? 1 : 0);
        conv_mma_kernel<<<dim3(64, 4), 256, MMA_SMEM>>>(main_b, proj_b, n);
        attn_kernel<<<dim3(BB, NHH), 256>>>(k0, v0, pos_w, pos_b, n);
        final_kernel<<<BB, 256>>>(out_w, out_b, ln_w, ln_b, c0, x, n,
                                  out, n == LNUM - 1 ? 1 : 0);
    }
}

// round 12
// speedup vs baseline: 2.0788x; 1.0706x over previous
#include <cuda_runtime.h>
#include <cuda_bf16.h>
#include <cstdint>

// Problem constants
#define LNUM 2
#define BB   128
#define CIN  64
#define EE   64
#define NHH  8
#define MEM  40
#define HD   8
#define THD  512         // HD*HW
#define PIX  64          // spatial size
#define C_MAIN 192       // CIN + 2E
#define C_PROJ 128       // CIN + E
#define CO_MAIN 320      // 5E
#define CO_PROJ 192      // 3E

// ---- warp-MMA GEMM config ----
#define NCHUNK 54               // 9 taps * 6 channel-blocks of 32
#define ASTR 40                 // padded bf16 row stride
#define TILE_ELEMS (128 * ASTR) // 5120 bf16 per tile
#define TILE_BYTES (TILE_ELEMS * 2)  // 10240 B
#define MMA_SMEM (8 * TILE_BYTES)    // 81920 B

// ---------------- scratch (device globals; no allocation) ----------------
__device__ unsigned g_ipk [BB * C_MAIN * PIX];  // packed bf16 (hi | lo<<16)
__device__ float g_gates[BB * CO_MAIN * PIX];   // (B,320,64)
__device__ float g_kqv  [BB * CO_PROJ * PIX];   // (B,192,64)
__device__ float g_attn [BB * EE * PIX];        // (B,64,64)
__device__ float g_ao   [BB * EE * PIX];        // out-conv + residual
__device__ float g_out  [BB * EE * PIX];        // (B,64,64)
__device__ float g_bias [BB * MEM];
__device__ float g_nd   [BB];
__device__ int   g_is_i32;
// pre-split bf16 weight tiles, plain [128 r][32 k]: [layer][mtile][chunk]
__device__ __nv_bfloat16 g_wA_hi[2 * 4 * NCHUNK * 4096];
__device__ __nv_bfloat16 g_wA_lo[2 * 4 * NCHUNK * 4096];

__device__ __forceinline__ float sigmoidf_(float v) {
    return 1.0f / (1.0f + __expf(-v));
}

__device__ __forceinline__ uint32_t smem_to_u32(const void* p) {
    uint32_t a;
    asm("{ .reg .u64 t; cvta.to.shared.u64 t, %1; cvt.u32.u64 %0, t; }"
        : "=r"(a) : "l"(p));
    return a;
}
__device__ __forceinline__ void ldsm4(uint32_t addr, uint32_t* r) {
    asm volatile("ldmatrix.sync.aligned.m8n8.x4.shared.b16 {%0,%1,%2,%3}, [%4];"
        : "=r"(r[0]), "=r"(r[1]), "=r"(r[2]), "=r"(r[3]) : "r"(addr));
}
__device__ __forceinline__ void mma16816(float* d, const uint32_t* a,
                                         uint32_t b0, uint32_t b1) {
    asm volatile(
        "mma.sync.aligned.m16n8k16.row.col.f32.bf16.bf16.f32 "
        "{%0,%1,%2,%3}, {%4,%5,%6,%7}, {%8,%9}, {%0,%1,%2,%3};"
        : "+f"(d[0]), "+f"(d[1]), "+f"(d[2]), "+f"(d[3])
        : "r"(a[0]), "r"(a[1]), "r"(a[2]), "r"(a[3]), "r"(b0), "r"(b1));
}
__device__ __forceinline__ void cpasync16(uint32_t dst, const void* src) {
    asm volatile("cp.async.cg.shared.global [%0], [%1], 16;"
                 :: "r"(dst), "l"(src) : "memory");
}
__device__ __forceinline__ void cpasync_commit() {
    asm volatile("cp.async.commit_group;" ::: "memory");
}
__device__ __forceinline__ void cpasync_wait0() {
    asm volatile("cp.async.wait_group 0;" ::: "memory");
}

// ---------------- dtype detection for bool inputs (parallel) ----------------
__global__ void detect_kernel(const int* __restrict__ sm) {
    __shared__ int bad;
    if (threadIdx.x == 0) bad = 0;
    __syncthreads();
    int anybad = 0;
    for (int i = threadIdx.x; i < (BB * MEM) / 4; i += 256) {
        int v = sm[i];
        if (v != 0 && v != 1) anybad = 1;
    }
    if (anybad) bad = 1;
    __syncthreads();
    if (threadIdx.x == 0) g_is_i32 = !bad;
}

__device__ __forceinline__ int read_bool(const void* p, int idx) {
    if (g_is_i32) return ((const int*)p)[idx] != 0;
    return ((const unsigned char*)p)[idx] != 0;
}

// ---------------- bias + notdone ----------------
__global__ void bias_kernel(const void* __restrict__ src_mask,
                            const void* __restrict__ notdone) {
    int t = blockIdx.x * 256 + threadIdx.x;
    if (t < BB) g_nd[t] = read_bool(notdone, t) ? 1.0f : 0.0f;
    if (t >= BB * MEM) return;
    int b = t / MEM, m = t - b * MEM;
    float v;
    if (m == MEM - 1) {
        v = 3.0f;  // MASK_B
    } else {
        bool masked = read_bool(src_mask, b * MEM + m + 1) || !read_bool(notdone, b);
        v = masked ? -1e9f : 0.0f;
    }
    g_bias[t] = v;
}

// ---------------- weight prepass: bf16 hi/lo split, [128 x 32] tiles ------
__global__ void wprep_kernel(const float* __restrict__ main_w,
                             const float* __restrict__ proj_w) {
    int id = blockIdx.x;
    int n = id / (4 * NCHUNK);
    int r2 = id % (4 * NCHUNK);
    int mtile = r2 / NCHUNK;
    int chunk = r2 % NCHUNK;
    int t  = chunk / 6;
    int c0 = (chunk % 6) * 32;
    __nv_bfloat16* dh = g_wA_hi + (size_t)id * 4096;
    __nv_bfloat16* dl = g_wA_lo + (size_t)id * 4096;
    for (int e = threadIdx.x; e < 4096; e += 256) {
        int r = e >> 5, kk = e & 31;
        int c = c0 + kk;
        int gco = mtile * 128 + r;
        float w = 0.0f;
        if (gco < CO_MAIN) {
            w = main_w[(((size_t)n * CO_MAIN + gco) * C_MAIN + c) * 9 + t];
        } else if (c < C_PROJ) {
            w = proj_w[(((size_t)n * CO_PROJ + (gco - CO_MAIN)) * C_PROJ + c) * 9 + t];
        }
        __nv_bfloat16 h = __float2bfloat16(w);
        __nv_bfloat16 l = __float2bfloat16(w - __bfloat162float(h));
        dh[e] = h;
        dl[e] = l;
    }
}

// ---------------- build concat input, packed bf16 hi/lo ----------------
__global__ void prep_kernel(const float* __restrict__ x,
                            const float* __restrict__ h0,
                            int n, int first) {
    int idx = blockIdx.x * 256 + threadIdx.x;
    if (idx >= BB * C_MAIN * PIX) return;
    int b = idx / (C_MAIN * PIX);
    int r = idx - b * (C_MAIN * PIX);
    int c = r >> 6;
    int p = r & 63;
    float nd = g_nd[b];
    float v;
    if (c < CIN) {
        v = x[b * (CIN * PIX) + r];
    } else if (c < CIN + EE) {
        int off = b * (EE * PIX) + (c - CIN) * PIX + p;
        if (first)
            v = h0[((size_t)(LNUM - 1) * BB + b) * (EE * PIX) + (c - CIN) * PIX + p] * nd;
        else
            v = g_out[off];
    } else {
        v = h0[((size_t)n * BB + b) * (EE * PIX) + (c - CIN - EE) * PIX + p] * nd;
    }
    __nv_bfloat16 h = __float2bfloat16(v);
    __nv_bfloat16 l = __float2bfloat16(v - __bfloat162float(h));
    g_ipk[idx] = (unsigned)__bfloat16_as_ushort(h)
               | ((unsigned)__bfloat16_as_ushort(l) << 16);
}

// ---------------- warp-MMA fused conv GEMM (K=32, 2 blocks/SM) -----------
__global__ void __launch_bounds__(256, 2)
conv_mma_kernel(const float* __restrict__ main_b,
                const float* __restrict__ proj_b,
                int n) {
    extern __shared__ __nv_bfloat16 smb[];
    uint32_t smb_u = smem_to_u32(smb);

    int tid = threadIdx.x;
    int lane = tid & 31, w = tid >> 5;
    int ntile = blockIdx.x, mtile = blockIdx.y;
    int b0 = ntile * 2;
    int mrow0 = (w >> 1) * 32;
    int nc0 = (w & 1) * 64;

    float acc[2][8][4];
#pragma unroll
    for (int mi = 0; mi < 2; mi++)
#pragma unroll
        for (int ni = 0; ni < 8; ni++)
#pragma unroll
            for (int j = 0; j < 4; j++) acc[mi][ni][j] = 0.0f;

    int lr = lane & 15, lc = lane >> 4;
    uint32_t aoff = (uint32_t)(((mrow0 + lr) * ASTR + lc * 8) * 2);
    uint32_t boff = (uint32_t)(((nc0 + lr) * ASTR + lc * 8) * 2);

    int brow = tid >> 1, half = tid & 1;
    int bb = brow >> 6, px = brow & 63;
    int yy = px >> 3, xx = px & 7;

    unsigned regBh[8], regBl[8];

    auto loadB = [&](int chunk) {
        int t = chunk / 6, c0 = (chunk % 6) * 32;
        int ty = t / 3, tx = t % 3;
        int iy = yy + ty - 1, ix = xx + tx - 1;
        bool valid = ((unsigned)iy < 8u) && ((unsigned)ix < 8u);
        const unsigned* src = g_ipk
            + ((size_t)(b0 + bb) * C_MAIN + c0 + half * 16) * PIX
            + (valid ? iy * 8 + ix : 0);
#pragma unroll
        for (int j = 0; j < 8; j++) {
            unsigned u0 = valid ? src[(2 * j) * PIX] : 0u;
            unsigned u1 = valid ? src[(2 * j + 1) * PIX] : 0u;
            regBh[j] = __byte_perm(u0, u1, 0x5410);
            regBl[j] = __byte_perm(u0, u1, 0x7632);
        }
    };
    auto issueA = [&](int chunk, int buf) {
        size_t toff = (((size_t)n * 4 + mtile) * NCHUNK + chunk) * 4096;
        const char* gh = (const char*)(g_wA_hi + toff);
        const char* gl = (const char*)(g_wA_lo + toff);
        uint32_t base = smb_u + (uint32_t)buf * 4 * TILE_BYTES;
#pragma unroll
        for (int i = 0; i < 2; i++) {
            int e = tid + 256 * i;
            int row = e >> 2, c16 = e & 3;
            uint32_t d = base + row * (ASTR * 2) + c16 * 16;
            cpasync16(d, gh + e * 16);
            cpasync16(d + TILE_BYTES, gl + e * 16);
        }
        cpasync_commit();
    };
    auto storeB = [&](int buf) {
        __nv_bfloat16* base = smb + (size_t)buf * 4 * TILE_ELEMS;
        unsigned* bh = (unsigned*)(base + 2 * TILE_ELEMS) + brow * (ASTR / 2) + half * 8;
        unsigned* bl = (unsigned*)(base + 3 * TILE_ELEMS) + brow * (ASTR / 2) + half * 8;
#pragma unroll
        for (int j = 0; j < 8; j++) { bh[j] = regBh[j]; bl[j] = regBl[j]; }
    };

    issueA(0, 0);
    loadB(0);
    storeB(0);
    cpasync_wait0();
    __syncthreads();

    for (int chunk = 0; chunk < NCHUNK; chunk++) {
        int buf = chunk & 1;
        if (chunk + 1 < NCHUNK) {
            issueA(chunk + 1, 1 - buf);
            loadB(chunk + 1);
        }

        uint32_t pbase = smb_u + (uint32_t)buf * 4 * TILE_BYTES;
        uint32_t pAh = pbase, pAl = pbase + TILE_BYTES;
        uint32_t pBh = pbase + 2 * TILE_BYTES, pBl = pbase + 3 * TILE_BYTES;
#pragma unroll
        for (int ks = 0; ks < 2; ks++) {
            uint32_t kb = (uint32_t)(ks * 32);
            uint32_t ah[2][4], al[2][4], bh[4][4], bl[4][4];
            ldsm4(pAh + aoff + kb, ah[0]);
            ldsm4(pAh + aoff + 16 * ASTR * 2 + kb, ah[1]);
            ldsm4(pAl + aoff + kb, al[0]);
            ldsm4(pAl + aoff + 16 * ASTR * 2 + kb, al[1]);
#pragma unroll
            for (int pn = 0; pn < 4; pn++) {
                ldsm4(pBh + boff + pn * 16 * ASTR * 2 + kb, bh[pn]);
                ldsm4(pBl + boff + pn * 16 * ASTR * 2 + kb, bl[pn]);
            }
#pragma unroll
            for (int mi = 0; mi < 2; mi++) {
#pragma unroll
                for (int ni = 0; ni < 8; ni++) {
                    int pn = ni >> 1, o = ni & 1;
                    mma16816(acc[mi][ni], ah[mi], bh[pn][o], bh[pn][o + 2]);
                    mma16816(acc[mi][ni], ah[mi], bl[pn][o], bl[pn][o + 2]);
                    mma16816(acc[mi][ni], al[mi], bh[pn][o], bh[pn][o + 2]);
                }
            }
        }
        if (chunk + 1 < NCHUNK) {
            storeB(1 - buf);
            cpasync_wait0();
            __syncthreads();
        }
    }

    // ---- epilogue: bias add + direct stores ----
    int batch = b0 + (w & 1);
#pragma unroll
    for (int mi = 0; mi < 2; mi++) {
#pragma unroll
        for (int rr = 0; rr < 2; rr++) {
            int r = mrow0 + mi * 16 + rr * 8 + (lane >> 2);
            int gr = mtile * 128 + r;
            bool ismain = (gr < CO_MAIN);
            float bias = ismain ? main_b[n * CO_MAIN + gr]
                                : proj_b[n * CO_PROJ + (gr - CO_MAIN)];
            float* dst = ismain
                ? g_gates + ((size_t)batch * CO_MAIN + gr) * PIX
                : g_kqv  + ((size_t)batch * CO_PROJ + (gr - CO_MAIN)) * PIX;
#pragma unroll
            for (int ni = 0; ni < 8; ni++) {
                int pxc = ni * 8 + (lane & 3) * 2;
                float2 v;
                v.x = acc[mi][ni][rr * 2 + 0] + bias;
                v.y = acc[mi][ni][rr * 2 + 1] + bias;
                *(float2*)&dst[pxc] = v;
            }
        }
    }
}

// ---------------- attention over rolling memory ----------------
__global__ void attn_kernel(const float* __restrict__ k0,
                            const float* __restrict__ v0,
                            const float* __restrict__ pos_w,
                            const float* __restrict__ pos_b,
                            int n) {
    int b = blockIdx.x;
    int h = blockIdx.y;
    int tid = threadIdx.x;
    __shared__ float q[THD], kn[THD], vn[THD];
    __shared__ float sc[MEM], wts[MEM];

    const float* kqv = g_kqv + (size_t)b * CO_PROJ * PIX;
    const float rscale = 0.044194173824159216f;  // 1/sqrt(512)
    for (int d = tid; d < THD; d += 256) {
        int hd = d >> 6, hw = d & 63;
        kn[d] = kqv[(h * 24 + hd) * PIX + hw];
        q[d]  = kqv[(h * 24 + 8 + hd) * PIX + hw] * rscale;
        vn[d] = kqv[(h * 24 + 16 + hd) * PIX + hw];
    }
    __syncthreads();

    const float* kb  = k0 + ((((size_t)n * BB + b) * NHH + h) * MEM) * THD;
    const float* pwb = pos_w + (size_t)n * MEM * (NHH * THD) + h * THD;
    int warp = tid >> 5, lane = tid & 31;
    for (int m = warp; m < MEM; m += 8) {
        const float* kr = (m < MEM - 1) ? (kb + (size_t)(m + 1) * THD) : kn;
        const float* pr = pwb + (size_t)m * (NHH * THD);
        float p = 0.0f;
        for (int d = lane; d < THD; d += 32)
            p = fmaf(q[d], kr[d] + pr[d], p);
#pragma unroll
        for (int o = 16; o; o >>= 1) p += __shfl_xor_sync(0xffffffffu, p, o);
        if (lane == 0)
            sc[m] = p + g_bias[b * MEM + m] + pos_b[(size_t)n * MEM * NHH + m * NHH + h];
    }
    __syncthreads();
    if (tid == 0) {
        float mx = sc[0];
#pragma unroll
        for (int m = 1; m < MEM; m++) mx = fmaxf(mx, sc[m]);
        float s = 0.0f;
#pragma unroll
        for (int m = 0; m < MEM; m++) {
            float e = __expf(sc[m] - mx);
            wts[m] = e;
            s += e;
        }
        float inv = 1.0f / s;
#pragma unroll
        for (int m = 0; m < MEM; m++) wts[m] *= inv;
    }
    __syncthreads();

    const float* vb = v0 + ((((size_t)n * BB + b) * NHH + h) * MEM) * THD;
    for (int d = tid; d < THD; d += 256) {
        float acc = wts[MEM - 1] * vn[d];
        for (int m = 0; m < MEM - 1; m++)
            acc = fmaf(wts[m], vb[(size_t)(m + 1) * THD + d], acc);
        int hd = d >> 6, hw = d & 63;
        g_attn[(size_t)b * (EE * PIX) + (h * 8 + hd) * PIX + hw] = acc;
    }
}

// ---------------- out conv + residual (parallel over 4 co-groups) --------
__global__ void __launch_bounds__(128, 8)
final_conv_kernel(const float* __restrict__ out_w,
                  const float* __restrict__ out_b,
                  const float* __restrict__ x,
                  int n) {
    __shared__ float sa[EE * 100];   // padded attn input
    int b = blockIdx.x;
    int g = blockIdx.y;              // co group: [g*16, g*16+16)
    int tid = threadIdx.x;           // 128

    for (int i = tid; i < EE * 100; i += 128) sa[i] = 0.0f;
    __syncthreads();
    const float* at = g_attn + (size_t)b * EE * PIX;
    for (int i = tid; i < EE * PIX; i += 128) {
        int c = i >> 6, p = i & 63;
        sa[c * 100 + ((p >> 3) + 1) * 10 + (p & 7) + 1] = at[i];
    }
    __syncthreads();

    int co = g * 16 + (tid >> 3);
    int row = tid & 7;
    const float* wc = out_w + ((size_t)n * EE + co) * EE * 9;
    float acc[8];
#pragma unroll
    for (int xx = 0; xx < 8; xx++) acc[xx] = 0.0f;
    for (int c = 0; c < EE; c++) {
        const float* s = sa + c * 100 + row * 10;
        const float* w = wc + c * 9;
        float w0 = w[0], w1 = w[1], w2 = w[2];
        float w3 = w[3], w4 = w[4], w5 = w[5];
        float w6 = w[6], w7 = w[7], w8 = w[8];
#pragma unroll
        for (int xx = 0; xx < 8; xx++) {
            float a = acc[xx];
            a = fmaf(s[xx],      w0, a);
            a = fmaf(s[xx + 1],  w1, a);
            a = fmaf(s[xx + 2],  w2, a);
            a = fmaf(s[10 + xx],     w3, a);
            a = fmaf(s[10 + xx + 1], w4, a);
            a = fmaf(s[10 + xx + 2], w5, a);
            a = fmaf(s[20 + xx],     w6, a);
            a = fmaf(s[20 + xx + 1], w7, a);
            a = fmaf(s[20 + xx + 2], w8, a);
            acc[xx] = a;
        }
    }
    float bb = out_b[n * EE + co];
    const float* xr = x + (size_t)b * EE * PIX;
    float* dst = g_ao + (size_t)b * EE * PIX + co * PIX + row * 8;
    int base = co * PIX + row * 8;
#pragma unroll
    for (int xx = 0; xx < 8; xx++)
        dst[xx] = acc[xx] + bb + xr[base + xx];
}

// ---------------- layernorm + LSTM combine ----------------
__global__ void final_ln_kernel(const float* __restrict__ ln_w,
                                const float* __restrict__ ln_b,
                                const float* __restrict__ c0,
                                int n, float* __restrict__ dst_last, int last) {
    __shared__ float red[16];
    __shared__ float s_mu, s_rv;
    int b = blockIdx.x;
    int tid = threadIdx.x;

    const float* aop = g_ao + (size_t)b * EE * PIX;
    float v16[16];
    float s1 = 0.0f, s2 = 0.0f;
#pragma unroll
    for (int j = 0; j < 16; j++) {
        float v = aop[tid + 256 * j];
        v16[j] = v;
        s1 += v;
        s2 += v * v;
    }
    int warp = tid >> 5, lane = tid & 31;
#pragma unroll
    for (int o = 16; o; o >>= 1) {
        s1 += __shfl_xor_sync(0xffffffffu, s1, o);
        s2 += __shfl_xor_sync(0xffffffffu, s2, o);
    }
    if (lane == 0) { red[warp] = s1; red[8 + warp] = s2; }
    __syncthreads();
    if (tid == 0) {
        float a = 0.0f, q2 = 0.0f;
#pragma unroll
        for (int w2 = 0; w2 < 8; w2++) { a += red[w2]; q2 += red[8 + w2]; }
        float mu = a * (1.0f / 4096.0f);
        float var = q2 * (1.0f / 4096.0f) - mu * mu;
        s_mu = mu;
        s_rv = rsqrtf(var + 1e-5f);
    }
    __syncthreads();
    float mu = s_mu, rv = s_rv;

    const float* gb = g_gates + (size_t)b * CO_MAIN * PIX;
    const float* cb = c0 + ((size_t)n * BB + b) * (EE * PIX);
    float nd = g_nd[b];
    float* dst = (last ? dst_last : g_out) + (size_t)b * EE * PIX;
    const float* lw = ln_w + (size_t)n * EE * PIX;
    const float* lb = ln_b + (size_t)n * EE * PIX;
#pragma unroll
    for (int j = 0; j < 16; j++) {
        int i = tid + 256 * j;
        int c = i >> 6, p = i & 63;
        float aon = (v16[j] - mu) * rv * lw[i] + lb[i];
        float gi = sigmoidf_(gb[(0 * EE + c) * PIX + p]);
        float gf = sigmoidf_(gb[(1 * EE + c) * PIX + p]);
        float go = sigmoidf_(gb[(2 * EE + c) * PIX + p]);
        float gg = tanhf(gb[(3 * EE + c) * PIX + p]);
        float ga = sigmoidf_(gb[(4 * EE + c) * PIX + p]);
        float cn = gf * (cb[i] * nd) + gi * gg + ga * tanhf(aon);
        dst[i] = go * tanhf(cn);
    }
}

// ---------------- launch ----------------
extern "C" void kernel_launch(void* const* d_in, const int* in_sizes, int n_in,
                              void* d_out, int out_size) {
    const float* x       = (const float*)d_in[0];
    const float* h0      = (const float*)d_in[1];
    const float* c0      = (const float*)d_in[2];
    const float* k0      = (const float*)d_in[3];
    const float* v0      = (const float*)d_in[4];
    const void*  src_mask = d_in[5];
    const void*  notdone  = d_in[6];
    const float* main_w  = (const float*)d_in[7];
    const float* main_b  = (const float*)d_in[8];
    const float* proj_w  = (const float*)d_in[9];
    const float* proj_b  = (const float*)d_in[10];
    const float* out_w   = (const float*)d_in[11];
    const float* out_b   = (const float*)d_in[12];
    const float* ln_w    = (const float*)d_in[13];
    const float* ln_b    = (const float*)d_in[14];
    const float* pos_w   = (const float*)d_in[15];
    const float* pos_b   = (const float*)d_in[16];
    float* out = (float*)d_out;

    cudaFuncSetAttribute(conv_mma_kernel,
                         cudaFuncAttributeMaxDynamicSharedMemorySize, MMA_SMEM);

    detect_kernel<<<1, 256>>>((const int*)src_mask);
    bias_kernel<<<(BB * MEM + 255) / 256, 256>>>(src_mask, notdone);
    wprep_kernel<<<2 * 4 * NCHUNK, 256>>>(main_w, proj_w);
    for (int n = 0; n < LNUM; n++) {
        int tot = BB * C_MAIN * PIX;
        prep_kernel<<<(tot + 255) / 256, 256>>>(x, h0, n, n == 0 ? 1 : 0);
        conv_mma_kernel<<<dim3(64, 4), 256, MMA_SMEM>>>(main_b, proj_b, n);
        attn_kernel<<<dim3(BB, NHH), 256>>>(k0, v0, pos_w, pos_b, n);
        final_conv_kernel<<<dim3(BB, 4), 128>>>(out_w, out_b, x, n);
        final_ln_kernel<<<BB, 256>>>(ln_w, ln_b, c0, n,
                                     out, n == LNUM - 1 ? 1 : 0);
    }
}

// round 13
// speedup vs baseline: 2.4711x; 1.1887x over previous
#include <cuda_runtime.h>
#include <cuda_fp16.h>
#include <cstdint>

// Problem constants
#define LNUM 2
#define BB   128
#define CIN  64
#define EE   64
#define NHH  8
#define MEM  40
#define HD   8
#define THD  512         // HD*HW
#define PIX  64          // spatial size
#define C_MAIN 192       // CIN + 2E
#define C_PROJ 128       // CIN + E
#define CO_MAIN 320      // 5E
#define CO_PROJ 192      // 3E

// ---- warp-MMA GEMM config ----
// Fused GEMM: M=512, N=8192 (128 b x 64 px), K=1728 (9 taps x 192 ch).
// Block: 256 thr (8 warps as 4m x 2n), tile M=128 x N=128, K chunk 32.
// fp16 2-term split: D = Ah*Bh + Al*Bh  (B single fp16).
#define NCHUNK 54               // 9 taps * 6 channel-blocks of 32
#define ASTR 40                 // padded fp16 row stride
#define TILE_ELEMS (128 * ASTR) // 5120 fp16 per tile
#define TILE_BYTES (TILE_ELEMS * 2)  // 10240 B
#define MMA_SMEM (6 * TILE_BYTES)    // 61440 B (2 bufs x {Ah,Al,Bh})

// ---------------- scratch (device globals; no allocation) ----------------
__device__ unsigned g_bpk [BB * (C_MAIN / 2) * PIX]; // fp16 channel-pair packed
__device__ float g_gates[BB * CO_MAIN * PIX];   // (B,320,64)
__device__ float g_kqv  [BB * CO_PROJ * PIX];   // (B,192,64)
__device__ float g_attn [BB * EE * PIX];        // (B,64,64)
__device__ float g_ao   [BB * EE * PIX];        // out-conv + residual
__device__ float g_out  [BB * EE * PIX];        // (B,64,64)
__device__ float g_bias [BB * MEM];
__device__ float g_nd   [BB];
__device__ int   g_is_i32;
// pre-split fp16 weight tiles, plain [128 r][32 k]: [layer][mtile][chunk]
__device__ __half g_wA_hi[2 * 4 * NCHUNK * 4096];
__device__ __half g_wA_lo[2 * 4 * NCHUNK * 4096];

__device__ __forceinline__ float sigmoidf_(float v) {
    return 1.0f / (1.0f + __expf(-v));
}

__device__ __forceinline__ uint32_t smem_to_u32(const void* p) {
    uint32_t a;
    asm("{ .reg .u64 t; cvta.to.shared.u64 t, %1; cvt.u32.u64 %0, t; }"
        : "=r"(a) : "l"(p));
    return a;
}
__device__ __forceinline__ void ldsm4(uint32_t addr, uint32_t* r) {
    asm volatile("ldmatrix.sync.aligned.m8n8.x4.shared.b16 {%0,%1,%2,%3}, [%4];"
        : "=r"(r[0]), "=r"(r[1]), "=r"(r[2]), "=r"(r[3]) : "r"(addr));
}
__device__ __forceinline__ void mma16816(float* d, const uint32_t* a,
                                         uint32_t b0, uint32_t b1) {
    asm volatile(
        "mma.sync.aligned.m16n8k16.row.col.f32.f16.f16.f32 "
        "{%0,%1,%2,%3}, {%4,%5,%6,%7}, {%8,%9}, {%0,%1,%2,%3};"
        : "+f"(d[0]), "+f"(d[1]), "+f"(d[2]), "+f"(d[3])
        : "r"(a[0]), "r"(a[1]), "r"(a[2]), "r"(a[3]), "r"(b0), "r"(b1));
}
__device__ __forceinline__ void cpasync16(uint32_t dst, const void* src) {
    asm volatile("cp.async.cg.shared.global [%0], [%1], 16;"
                 :: "r"(dst), "l"(src) : "memory");
}
__device__ __forceinline__ void cpasync_commit() {
    asm volatile("cp.async.commit_group;" ::: "memory");
}
__device__ __forceinline__ void cpasync_wait0() {
    asm volatile("cp.async.wait_group 0;" ::: "memory");
}

// ---------------- dtype detection for bool inputs (parallel) ----------------
__global__ void detect_kernel(const int* __restrict__ sm) {
    __shared__ int bad;
    if (threadIdx.x == 0) bad = 0;
    __syncthreads();
    int anybad = 0;
    for (int i = threadIdx.x; i < (BB * MEM) / 4; i += 256) {
        int v = sm[i];
        if (v != 0 && v != 1) anybad = 1;
    }
    if (anybad) bad = 1;
    __syncthreads();
    if (threadIdx.x == 0) g_is_i32 = !bad;
}

__device__ __forceinline__ int read_bool(const void* p, int idx) {
    if (g_is_i32) return ((const int*)p)[idx] != 0;
    return ((const unsigned char*)p)[idx] != 0;
}

// ---------------- bias + notdone ----------------
__global__ void bias_kernel(const void* __restrict__ src_mask,
                            const void* __restrict__ notdone) {
    int t = blockIdx.x * 256 + threadIdx.x;
    if (t < BB) g_nd[t] = read_bool(notdone, t) ? 1.0f : 0.0f;
    if (t >= BB * MEM) return;
    int b = t / MEM, m = t - b * MEM;
    float v;
    if (m == MEM - 1) {
        v = 3.0f;  // MASK_B
    } else {
        bool masked = read_bool(src_mask, b * MEM + m + 1) || !read_bool(notdone, b);
        v = masked ? -1e9f : 0.0f;
    }
    g_bias[t] = v;
}

// ---------------- weight prepass: fp16 hi/lo split, [128 x 32] tiles ------
__global__ void wprep_kernel(const float* __restrict__ main_w,
                             const float* __restrict__ proj_w) {
    int id = blockIdx.x;
    int n = id / (4 * NCHUNK);
    int r2 = id % (4 * NCHUNK);
    int mtile = r2 / NCHUNK;
    int chunk = r2 % NCHUNK;
    int t  = chunk / 6;
    int c0 = (chunk % 6) * 32;
    __half* dh = g_wA_hi + (size_t)id * 4096;
    __half* dl = g_wA_lo + (size_t)id * 4096;
    for (int e = threadIdx.x; e < 4096; e += 256) {
        int r = e >> 5, kk = e & 31;
        int c = c0 + kk;
        int gco = mtile * 128 + r;
        float w = 0.0f;
        if (gco < CO_MAIN) {
            w = main_w[(((size_t)n * CO_MAIN + gco) * C_MAIN + c) * 9 + t];
        } else if (c < C_PROJ) {
            w = proj_w[(((size_t)n * CO_PROJ + (gco - CO_MAIN)) * C_PROJ + c) * 9 + t];
        }
        __half h = __float2half_rn(w);
        __half l = __float2half_rn(w - __half2float(h));
        dh[e] = h;
        dl[e] = l;
    }
}

// ---------------- build concat input, fp16 channel-pair packed -----------
__global__ void prep_kernel(const float* __restrict__ x,
                            const float* __restrict__ h0,
                            int n, int first) {
    int idx = blockIdx.x * 256 + threadIdx.x;
    if (idx >= BB * (C_MAIN / 2) * PIX) return;
    int b = idx / ((C_MAIN / 2) * PIX);
    int r = idx - b * ((C_MAIN / 2) * PIX);
    int cp = r >> 6;
    int p = r & 63;
    float nd = g_nd[b];
    float vv[2];
#pragma unroll
    for (int s = 0; s < 2; s++) {
        int c = 2 * cp + s;
        float v;
        if (c < CIN) {
            v = x[b * (CIN * PIX) + c * PIX + p];
        } else if (c < CIN + EE) {
            if (first)
                v = h0[((size_t)(LNUM - 1) * BB + b) * (EE * PIX) + (c - CIN) * PIX + p] * nd;
            else
                v = g_out[(size_t)b * (EE * PIX) + (c - CIN) * PIX + p];
        } else {
            v = h0[((size_t)n * BB + b) * (EE * PIX) + (c - CIN - EE) * PIX + p] * nd;
        }
        vv[s] = v;
    }
    __half2 hp = make_half2(__float2half_rn(vv[0]), __float2half_rn(vv[1]));
    g_bpk[idx] = *(unsigned*)&hp;
}

// ---------------- warp-MMA fused conv GEMM (fp16 2-term) -----------------
__global__ void __launch_bounds__(256, 2)
conv_mma_kernel(const float* __restrict__ main_b,
                const float* __restrict__ proj_b,
                int n) {
    extern __shared__ __half smb[];
    uint32_t smb_u = smem_to_u32(smb);

    int tid = threadIdx.x;
    int lane = tid & 31, w = tid >> 5;
    int ntile = blockIdx.x, mtile = blockIdx.y;
    int b0 = ntile * 2;
    int mrow0 = (w >> 1) * 32;
    int nc0 = (w & 1) * 64;

    float acc[2][8][4];
#pragma unroll
    for (int mi = 0; mi < 2; mi++)
#pragma unroll
        for (int ni = 0; ni < 8; ni++)
#pragma unroll
            for (int j = 0; j < 4; j++) acc[mi][ni][j] = 0.0f;

    int lr = lane & 15, lc = lane >> 4;
    uint32_t aoff = (uint32_t)(((mrow0 + lr) * ASTR + lc * 8) * 2);
    uint32_t boff = (uint32_t)(((nc0 + lr) * ASTR + lc * 8) * 2);

    // B-staging geometry (thread -> one B row half: 16 channels = 8 pairs)
    int brow = tid >> 1, half = tid & 1;
    int bb = brow >> 6, px = brow & 63;
    int yy = px >> 3, xx = px & 7;

    unsigned regB[8];

    auto loadB = [&](int chunk) {
        int t = chunk / 6;
        int cp0 = (chunk % 6) * 16;   // channel-pair base
        int ty = t / 3, tx = t % 3;
        int iy = yy + ty - 1, ix = xx + tx - 1;
        bool valid = ((unsigned)iy < 8u) && ((unsigned)ix < 8u);
        const unsigned* src = g_bpk
            + ((size_t)(b0 + bb) * (C_MAIN / 2) + cp0 + half * 8) * PIX
            + (valid ? iy * 8 + ix : 0);
#pragma unroll
        for (int j = 0; j < 8; j++)
            regB[j] = valid ? src[j * PIX] : 0u;
    };
    auto issueA = [&](int chunk, int buf) {
        size_t toff = (((size_t)n * 4 + mtile) * NCHUNK + chunk) * 4096;
        const char* gh = (const char*)(g_wA_hi + toff);
        const char* gl = (const char*)(g_wA_lo + toff);
        uint32_t base = smb_u + (uint32_t)buf * 3 * TILE_BYTES;
#pragma unroll
        for (int i = 0; i < 2; i++) {
            int e = tid + 256 * i;          // 512 16B chunks per tile
            int row = e >> 2, c16 = e & 3;
            uint32_t d = base + row * (ASTR * 2) + c16 * 16;
            cpasync16(d, gh + e * 16);
            cpasync16(d + TILE_BYTES, gl + e * 16);
        }
        cpasync_commit();
    };
    auto storeB = [&](int buf) {
        __half* base = smb + (size_t)buf * 3 * TILE_ELEMS;
        unsigned* bh = (unsigned*)(base + 2 * TILE_ELEMS) + brow * (ASTR / 2) + half * 8;
#pragma unroll
        for (int j = 0; j < 8; j++) bh[j] = regB[j];
    };

    issueA(0, 0);
    loadB(0);
    storeB(0);
    cpasync_wait0();
    __syncthreads();

    for (int chunk = 0; chunk < NCHUNK; chunk++) {
        int buf = chunk & 1;
        if (chunk + 1 < NCHUNK) {
            issueA(chunk + 1, 1 - buf);
            loadB(chunk + 1);
        }

        uint32_t pbase = smb_u + (uint32_t)buf * 3 * TILE_BYTES;
        uint32_t pAh = pbase, pAl = pbase + TILE_BYTES;
        uint32_t pBh = pbase + 2 * TILE_BYTES;
#pragma unroll
        for (int ks = 0; ks < 2; ks++) {
            uint32_t kb = (uint32_t)(ks * 32);
            uint32_t ah[2][4], al[2][4], bh[4][4];
            ldsm4(pAh + aoff + kb, ah[0]);
            ldsm4(pAh + aoff + 16 * ASTR * 2 + kb, ah[1]);
            ldsm4(pAl + aoff + kb, al[0]);
            ldsm4(pAl + aoff + 16 * ASTR * 2 + kb, al[1]);
#pragma unroll
            for (int pn = 0; pn < 4; pn++)
                ldsm4(pBh + boff + pn * 16 * ASTR * 2 + kb, bh[pn]);
#pragma unroll
            for (int mi = 0; mi < 2; mi++) {
#pragma unroll
                for (int ni = 0; ni < 8; ni++) {
                    int pn = ni >> 1, o = ni & 1;
                    mma16816(acc[mi][ni], ah[mi], bh[pn][o], bh[pn][o + 2]);
                    mma16816(acc[mi][ni], al[mi], bh[pn][o], bh[pn][o + 2]);
                }
            }
        }
        if (chunk + 1 < NCHUNK) {
            storeB(1 - buf);
            cpasync_wait0();
            __syncthreads();
        }
    }

    // ---- epilogue: bias add + direct stores ----
    int batch = b0 + (w & 1);
#pragma unroll
    for (int mi = 0; mi < 2; mi++) {
#pragma unroll
        for (int rr = 0; rr < 2; rr++) {
            int r = mrow0 + mi * 16 + rr * 8 + (lane >> 2);
            int gr = mtile * 128 + r;
            bool ismain = (gr < CO_MAIN);
            float bias = ismain ? main_b[n * CO_MAIN + gr]
                                : proj_b[n * CO_PROJ + (gr - CO_MAIN)];
            float* dst = ismain
                ? g_gates + ((size_t)batch * CO_MAIN + gr) * PIX
                : g_kqv  + ((size_t)batch * CO_PROJ + (gr - CO_MAIN)) * PIX;
#pragma unroll
            for (int ni = 0; ni < 8; ni++) {
                int pxc = ni * 8 + (lane & 3) * 2;
                float2 v;
                v.x = acc[mi][ni][rr * 2 + 0] + bias;
                v.y = acc[mi][ni][rr * 2 + 1] + bias;
                *(float2*)&dst[pxc] = v;
            }
        }
    }
}

// ---------------- attention over rolling memory ----------------
__global__ void attn_kernel(const float* __restrict__ k0,
                            const float* __restrict__ v0,
                            const float* __restrict__ pos_w,
                            const float* __restrict__ pos_b,
                            int n) {
    int b = blockIdx.x;
    int h = blockIdx.y;
    int tid = threadIdx.x;
    __shared__ float q[THD], kn[THD], vn[THD];
    __shared__ float sc[MEM], wts[MEM];

    const float* kqv = g_kqv + (size_t)b * CO_PROJ * PIX;
    const float rscale = 0.044194173824159216f;  // 1/sqrt(512)
    for (int d = tid; d < THD; d += 256) {
        int hd = d >> 6, hw = d & 63;
        kn[d] = kqv[(h * 24 + hd) * PIX + hw];
        q[d]  = kqv[(h * 24 + 8 + hd) * PIX + hw] * rscale;
        vn[d] = kqv[(h * 24 + 16 + hd) * PIX + hw];
    }
    __syncthreads();

    const float* kb  = k0 + ((((size_t)n * BB + b) * NHH + h) * MEM) * THD;
    const float* pwb = pos_w + (size_t)n * MEM * (NHH * THD) + h * THD;
    int warp = tid >> 5, lane = tid & 31;
    for (int m = warp; m < MEM; m += 8) {
        const float* kr = (m < MEM - 1) ? (kb + (size_t)(m + 1) * THD) : kn;
        const float* pr = pwb + (size_t)m * (NHH * THD);
        float p = 0.0f;
        for (int d = lane; d < THD; d += 32)
            p = fmaf(q[d], kr[d] + pr[d], p);
#pragma unroll
        for (int o = 16; o; o >>= 1) p += __shfl_xor_sync(0xffffffffu, p, o);
        if (lane == 0)
            sc[m] = p + g_bias[b * MEM + m] + pos_b[(size_t)n * MEM * NHH + m * NHH + h];
    }
    __syncthreads();
    if (tid == 0) {
        float mx = sc[0];
#pragma unroll
        for (int m = 1; m < MEM; m++) mx = fmaxf(mx, sc[m]);
        float s = 0.0f;
#pragma unroll
        for (int m = 0; m < MEM; m++) {
            float e = __expf(sc[m] - mx);
            wts[m] = e;
            s += e;
        }
        float inv = 1.0f / s;
#pragma unroll
        for (int m = 0; m < MEM; m++) wts[m] *= inv;
    }
    __syncthreads();

    const float* vb = v0 + ((((size_t)n * BB + b) * NHH + h) * MEM) * THD;
    for (int d = tid; d < THD; d += 256) {
        float acc = wts[MEM - 1] * vn[d];
        for (int m = 0; m < MEM - 1; m++)
            acc = fmaf(wts[m], vb[(size_t)(m + 1) * THD + d], acc);
        int hd = d >> 6, hw = d & 63;
        g_attn[(size_t)b * (EE * PIX) + (h * 8 + hd) * PIX + hw] = acc;
    }
}

// ---------------- out conv + residual (parallel over 4 co-groups) --------
__global__ void __launch_bounds__(128, 8)
final_conv_kernel(const float* __restrict__ out_w,
                  const float* __restrict__ out_b,
                  const float* __restrict__ x,
                  int n) {
    __shared__ float sa[EE * 100];   // padded attn input
    int b = blockIdx.x;
    int g = blockIdx.y;              // co group: [g*16, g*16+16)
    int tid = threadIdx.x;           // 128

    for (int i = tid; i < EE * 100; i += 128) sa[i] = 0.0f;
    __syncthreads();
    const float* at = g_attn + (size_t)b * EE * PIX;
    for (int i = tid; i < EE * PIX; i += 128) {
        int c = i >> 6, p = i & 63;
        sa[c * 100 + ((p >> 3) + 1) * 10 + (p & 7) + 1] = at[i];
    }
    __syncthreads();

    int co = g * 16 + (tid >> 3);
    int row = tid & 7;
    const float* wc = out_w + ((size_t)n * EE + co) * EE * 9;
    float acc[8];
#pragma unroll
    for (int xx = 0; xx < 8; xx++) acc[xx] = 0.0f;
    for (int c = 0; c < EE; c++) {
        const float* s = sa + c * 100 + row * 10;
        const float* w = wc + c * 9;
        float w0 = w[0], w1 = w[1], w2 = w[2];
        float w3 = w[3], w4 = w[4], w5 = w[5];
        float w6 = w[6], w7 = w[7], w8 = w[8];
#pragma unroll
        for (int xx = 0; xx < 8; xx++) {
            float a = acc[xx];
            a = fmaf(s[xx],      w0, a);
            a = fmaf(s[xx + 1],  w1, a);
            a = fmaf(s[xx + 2],  w2, a);
            a = fmaf(s[10 + xx],     w3, a);
            a = fmaf(s[10 + xx + 1], w4, a);
            a = fmaf(s[10 + xx + 2], w5, a);
            a = fmaf(s[20 + xx],     w6, a);
            a = fmaf(s[20 + xx + 1], w7, a);
            a = fmaf(s[20 + xx + 2], w8, a);
            acc[xx] = a;
        }
    }
    float bb = out_b[n * EE + co];
    const float* xr = x + (size_t)b * EE * PIX;
    float* dst = g_ao + (size_t)b * EE * PIX + co * PIX + row * 8;
    int base = co * PIX + row * 8;
#pragma unroll
    for (int xx = 0; xx < 8; xx++)
        dst[xx] = acc[xx] + bb + xr[base + xx];
}

// ---------------- layernorm + LSTM combine ----------------
__global__ void final_ln_kernel(const float* __restrict__ ln_w,
                                const float* __restrict__ ln_b,
                                const float* __restrict__ c0,
                                int n, float* __restrict__ dst_last, int last) {
    __shared__ float red[16];
    __shared__ float s_mu, s_rv;
    int b = blockIdx.x;
    int tid = threadIdx.x;

    const float* aop = g_ao + (size_t)b * EE * PIX;
    float v16[16];
    float s1 = 0.0f, s2 = 0.0f;
#pragma unroll
    for (int j = 0; j < 16; j++) {
        float v = aop[tid + 256 * j];
        v16[j] = v;
        s1 += v;
        s2 += v * v;
    }
    int warp = tid >> 5, lane = tid & 31;
#pragma unroll
    for (int o = 16; o; o >>= 1) {
        s1 += __shfl_xor_sync(0xffffffffu, s1, o);
        s2 += __shfl_xor_sync(0xffffffffu, s2, o);
    }
    if (lane == 0) { red[warp] = s1; red[8 + warp] = s2; }
    __syncthreads();
    if (tid == 0) {
        float a = 0.0f, q2 = 0.0f;
#pragma unroll
        for (int w2 = 0; w2 < 8; w2++) { a += red[w2]; q2 += red[8 + w2]; }
        float mu = a * (1.0f / 4096.0f);
        float var = q2 * (1.0f / 4096.0f) - mu * mu;
        s_mu = mu;
        s_rv = rsqrtf(var + 1e-5f);
    }
    __syncthreads();
    float mu = s_mu, rv = s_rv;

    const float* gb = g_gates + (size_t)b * CO_MAIN * PIX;
    const float* cb = c0 + ((size_t)n * BB + b) * (EE * PIX);
    float nd = g_nd[b];
    float* dst = (last ? dst_last : g_out) + (size_t)b * EE * PIX;
    const float* lw = ln_w + (size_t)n * EE * PIX;
    const float* lb = ln_b + (size_t)n * EE * PIX;
#pragma unroll
    for (int j = 0; j < 16; j++) {
        int i = tid + 256 * j;
        int c = i >> 6, p = i & 63;
        float aon = (v16[j] - mu) * rv * lw[i] + lb[i];
        float gi = sigmoidf_(gb[(0 * EE + c) * PIX + p]);
        float gf = sigmoidf_(gb[(1 * EE + c) * PIX + p]);
        float go = sigmoidf_(gb[(2 * EE + c) * PIX + p]);
        float gg = tanhf(gb[(3 * EE + c) * PIX + p]);
        float ga = sigmoidf_(gb[(4 * EE + c) * PIX + p]);
        float cn = gf * (cb[i] * nd) + gi * gg + ga * tanhf(aon);
        dst[i] = go * tanhf(cn);
    }
}

// ---------------- launch ----------------
extern "C" void kernel_launch(void* const* d_in, const int* in_sizes, int n_in,
                              void* d_out, int out_size) {
    const float* x       = (const float*)d_in[0];
    const float* h0      = (const float*)d_in[1];
    const float* c0      = (const float*)d_in[2];
    const float* k0      = (const float*)d_in[3];
    const float* v0      = (const float*)d_in[4];
    const void*  src_mask = d_in[5];
    const void*  notdone  = d_in[6];
    const float* main_w  = (const float*)d_in[7];
    const float* main_b  = (const float*)d_in[8];
    const float* proj_w  = (const float*)d_in[9];
    const float* proj_b  = (const float*)d_in[10];
    const float* out_w   = (const float*)d_in[11];
    const float* out_b   = (const float*)d_in[12];
    const float* ln_w    = (const float*)d_in[13];
    const float* ln_b    = (const float*)d_in[14];
    const float* pos_w   = (const float*)d_in[15];
    const float* pos_b   = (const float*)d_in[16];
    float* out = (float*)d_out;

    cudaFuncSetAttribute(conv_mma_kernel,
                         cudaFuncAttributeMaxDynamicSharedMemorySize, MMA_SMEM);

    detect_kernel<<<1, 256>>>((const int*)src_mask);
    bias_kernel<<<(BB * MEM + 255) / 256, 256>>>(src_mask, notdone);
    wprep_kernel<<<2 * 4 * NCHUNK, 256>>>(main_w, proj_w);
    for (int n = 0; n < LNUM; n++) {
        int tot = BB * (C_MAIN / 2) * PIX;
        prep_kernel<<<(tot + 255) / 256, 256>>>(x, h0, n, n == 0 ? 1 : 0);
        conv_mma_kernel<<<dim3(64, 4), 256, MMA_SMEM>>>(main_b, proj_b, n);
        attn_kernel<<<dim3(BB, NHH), 256>>>(k0, v0, pos_w, pos_b, n);
        final_conv_kernel<<<dim3(BB, 4), 128>>>(out_w, out_b, x, n);
        final_ln_kernel<<<BB, 256>>>(ln_w, ln_b, c0, n,
                                     out, n == LNUM - 1 ? 1 : 0);
    }
}

// round 14
// speedup vs baseline: 3.0887x; 1.2499x over previous
#include <cuda_runtime.h>
#include <cuda_fp16.h>
#include <cstdint>

// Problem constants
#define LNUM 2
#define BB   128
#define CIN  64
#define EE   64
#define NHH  8
#define MEM  40
#define HD   8
#define THD  512         // HD*HW
#define PIX  64          // spatial size
#define C_MAIN 192       // CIN + 2E
#define C_PROJ 128       // CIN + E
#define CO_MAIN 320      // 5E
#define CO_PROJ 192      // 3E

// ---- warp-MMA GEMM config ----
// Fused GEMM: M=512, N=8192 (128 b x 64 px), K=1728 (9 taps x 192 ch).
// Block: 256 thr (8 warps as 4m x 2n), tile M=128 x N=128, K chunk 32.
// Plain fp16 GEMM (A and B single fp16, fp32 accum).
#define NCHUNK 54               // 9 taps * 6 channel-blocks of 32
#define ASTR 40                 // padded fp16 row stride
#define TILE_ELEMS (128 * ASTR) // 5120 fp16 per tile
#define TILE_BYTES (TILE_ELEMS * 2)  // 10240 B
#define MMA_SMEM (4 * TILE_BYTES)    // 40960 B (2 bufs x {A,B})

// ---------------- scratch (device globals; no allocation) ----------------
__device__ unsigned g_bpk [BB * (C_MAIN / 2) * PIX]; // fp16 channel-pair packed
__device__ float g_gates[BB * CO_MAIN * PIX];   // (B,320,64)
__device__ float g_kqv  [BB * CO_PROJ * PIX];   // (B,192,64)
__device__ float g_attn [BB * EE * PIX];        // (B,64,64)
__device__ float g_ao   [BB * EE * PIX];        // out-conv + residual
__device__ float g_out  [BB * EE * PIX];        // (B,64,64)
__device__ float g_bias [BB * MEM];
__device__ float g_nd   [BB];
__device__ int   g_is_i32;
// fp16 weight tiles, plain [128 r][32 k]: [layer][mtile][chunk]
__device__ __half g_wA[2 * 4 * NCHUNK * 4096];

__device__ __forceinline__ float sigmoidf_(float v) {
    return 1.0f / (1.0f + __expf(-v));
}

__device__ __forceinline__ uint32_t smem_to_u32(const void* p) {
    uint32_t a;
    asm("{ .reg .u64 t; cvta.to.shared.u64 t, %1; cvt.u32.u64 %0, t; }"
        : "=r"(a) : "l"(p));
    return a;
}
__device__ __forceinline__ void ldsm4(uint32_t addr, uint32_t* r) {
    asm volatile("ldmatrix.sync.aligned.m8n8.x4.shared.b16 {%0,%1,%2,%3}, [%4];"
        : "=r"(r[0]), "=r"(r[1]), "=r"(r[2]), "=r"(r[3]) : "r"(addr));
}
__device__ __forceinline__ void mma16816(float* d, const uint32_t* a,
                                         uint32_t b0, uint32_t b1) {
    asm volatile(
        "mma.sync.aligned.m16n8k16.row.col.f32.f16.f16.f32 "
        "{%0,%1,%2,%3}, {%4,%5,%6,%7}, {%8,%9}, {%0,%1,%2,%3};"
        : "+f"(d[0]), "+f"(d[1]), "+f"(d[2]), "+f"(d[3])
        : "r"(a[0]), "r"(a[1]), "r"(a[2]), "r"(a[3]), "r"(b0), "r"(b1));
}
__device__ __forceinline__ void cpasync16(uint32_t dst, const void* src) {
    asm volatile("cp.async.cg.shared.global [%0], [%1], 16;"
                 :: "r"(dst), "l"(src) : "memory");
}
__device__ __forceinline__ void cpasync_commit() {
    asm volatile("cp.async.commit_group;" ::: "memory");
}
__device__ __forceinline__ void cpasync_wait0() {
    asm volatile("cp.async.wait_group 0;" ::: "memory");
}

// ---------------- dtype detection for bool inputs (parallel) ----------------
__global__ void detect_kernel(const int* __restrict__ sm) {
    __shared__ int bad;
    if (threadIdx.x == 0) bad = 0;
    __syncthreads();
    int anybad = 0;
    for (int i = threadIdx.x; i < (BB * MEM) / 4; i += 256) {
        int v = sm[i];
        if (v != 0 && v != 1) anybad = 1;
    }
    if (anybad) bad = 1;
    __syncthreads();
    if (threadIdx.x == 0) g_is_i32 = !bad;
}

__device__ __forceinline__ int read_bool(const void* p, int idx) {
    if (g_is_i32) return ((const int*)p)[idx] != 0;
    return ((const unsigned char*)p)[idx] != 0;
}

// ---------------- bias + notdone ----------------
__global__ void bias_kernel(const void* __restrict__ src_mask,
                            const void* __restrict__ notdone) {
    int t = blockIdx.x * 256 + threadIdx.x;
    if (t < BB) g_nd[t] = read_bool(notdone, t) ? 1.0f : 0.0f;
    if (t >= BB * MEM) return;
    int b = t / MEM, m = t - b * MEM;
    float v;
    if (m == MEM - 1) {
        v = 3.0f;  // MASK_B
    } else {
        bool masked = read_bool(src_mask, b * MEM + m + 1) || !read_bool(notdone, b);
        v = masked ? -1e9f : 0.0f;
    }
    g_bias[t] = v;
}

// ---------------- weight prepass: fp16 tiles [128 x 32] -------------------
__global__ void wprep_kernel(const float* __restrict__ main_w,
                             const float* __restrict__ proj_w) {
    int id = blockIdx.x;
    int n = id / (4 * NCHUNK);
    int r2 = id % (4 * NCHUNK);
    int mtile = r2 / NCHUNK;
    int chunk = r2 % NCHUNK;
    int t  = chunk / 6;
    int c0 = (chunk % 6) * 32;
    __half* dh = g_wA + (size_t)id * 4096;
    for (int e = threadIdx.x; e < 4096; e += 256) {
        int r = e >> 5, kk = e & 31;
        int c = c0 + kk;
        int gco = mtile * 128 + r;
        float w = 0.0f;
        if (gco < CO_MAIN) {
            w = main_w[(((size_t)n * CO_MAIN + gco) * C_MAIN + c) * 9 + t];
        } else if (c < C_PROJ) {
            w = proj_w[(((size_t)n * CO_PROJ + (gco - CO_MAIN)) * C_PROJ + c) * 9 + t];
        }
        dh[e] = __float2half_rn(w);
    }
}

// ---------------- build concat input, fp16 channel-pair packed -----------
__global__ void prep_kernel(const float* __restrict__ x,
                            const float* __restrict__ h0,
                            int n, int first) {
    int idx = blockIdx.x * 256 + threadIdx.x;
    if (idx >= BB * (C_MAIN / 2) * PIX) return;
    int b = idx / ((C_MAIN / 2) * PIX);
    int r = idx - b * ((C_MAIN / 2) * PIX);
    int cp = r >> 6;
    int p = r & 63;
    float nd = g_nd[b];
    float vv[2];
#pragma unroll
    for (int s = 0; s < 2; s++) {
        int c = 2 * cp + s;
        float v;
        if (c < CIN) {
            v = x[b * (CIN * PIX) + c * PIX + p];
        } else if (c < CIN + EE) {
            if (first)
                v = h0[((size_t)(LNUM - 1) * BB + b) * (EE * PIX) + (c - CIN) * PIX + p] * nd;
            else
                v = g_out[(size_t)b * (EE * PIX) + (c - CIN) * PIX + p];
        } else {
            v = h0[((size_t)n * BB + b) * (EE * PIX) + (c - CIN - EE) * PIX + p] * nd;
        }
        vv[s] = v;
    }
    __half2 hp = make_half2(__float2half_rn(vv[0]), __float2half_rn(vv[1]));
    g_bpk[idx] = *(unsigned*)&hp;
}

// ---------------- warp-MMA fused conv GEMM (plain fp16) ------------------
__global__ void __launch_bounds__(256, 2)
conv_mma_kernel(const float* __restrict__ main_b,
                const float* __restrict__ proj_b,
                int n) {
    extern __shared__ __half smb[];
    uint32_t smb_u = smem_to_u32(smb);

    int tid = threadIdx.x;
    int lane = tid & 31, w = tid >> 5;
    int ntile = blockIdx.x, mtile = blockIdx.y;
    int b0 = ntile * 2;
    int mrow0 = (w >> 1) * 32;
    int nc0 = (w & 1) * 64;

    float acc[2][8][4];
#pragma unroll
    for (int mi = 0; mi < 2; mi++)
#pragma unroll
        for (int ni = 0; ni < 8; ni++)
#pragma unroll
            for (int j = 0; j < 4; j++) acc[mi][ni][j] = 0.0f;

    int lr = lane & 15, lc = lane >> 4;
    uint32_t aoff = (uint32_t)(((mrow0 + lr) * ASTR + lc * 8) * 2);
    uint32_t boff = (uint32_t)(((nc0 + lr) * ASTR + lc * 8) * 2);

    // B-staging geometry (thread -> one B row half: 16 channels = 8 pairs)
    int brow = tid >> 1, half = tid & 1;
    int bb = brow >> 6, px = brow & 63;
    int yy = px >> 3, xx = px & 7;

    unsigned regB[8];

    auto loadB = [&](int chunk) {
        int t = chunk / 6;
        int cp0 = (chunk % 6) * 16;   // channel-pair base
        int ty = t / 3, tx = t % 3;
        int iy = yy + ty - 1, ix = xx + tx - 1;
        bool valid = ((unsigned)iy < 8u) && ((unsigned)ix < 8u);
        const unsigned* src = g_bpk
            + ((size_t)(b0 + bb) * (C_MAIN / 2) + cp0 + half * 8) * PIX
            + (valid ? iy * 8 + ix : 0);
#pragma unroll
        for (int j = 0; j < 8; j++)
            regB[j] = valid ? src[j * PIX] : 0u;
    };
    auto issueA = [&](int chunk, int buf) {
        size_t toff = (((size_t)n * 4 + mtile) * NCHUNK + chunk) * 4096;
        const char* gh = (const char*)(g_wA + toff);
        uint32_t base = smb_u + (uint32_t)buf * 2 * TILE_BYTES;
        {
            int e = tid;                    // 512 16B chunks, 2 per thread
            int row = e >> 2, c16 = e & 3;
            cpasync16(base + row * (ASTR * 2) + c16 * 16, gh + e * 16);
            e = tid + 256;
            row = e >> 2; c16 = e & 3;
            cpasync16(base + row * (ASTR * 2) + c16 * 16, gh + e * 16);
        }
        cpasync_commit();
    };
    auto storeB = [&](int buf) {
        __half* base = smb + (size_t)buf * 2 * TILE_ELEMS;
        unsigned* bh = (unsigned*)(base + TILE_ELEMS) + brow * (ASTR / 2) + half * 8;
#pragma unroll
        for (int j = 0; j < 8; j++) bh[j] = regB[j];
    };

    issueA(0, 0);
    loadB(0);
    storeB(0);
    cpasync_wait0();
    __syncthreads();

    for (int chunk = 0; chunk < NCHUNK; chunk++) {
        int buf = chunk & 1;
        if (chunk + 1 < NCHUNK) {
            issueA(chunk + 1, 1 - buf);
            loadB(chunk + 1);
        }

        uint32_t pbase = smb_u + (uint32_t)buf * 2 * TILE_BYTES;
        uint32_t pA = pbase, pB = pbase + TILE_BYTES;
#pragma unroll
        for (int ks = 0; ks < 2; ks++) {
            uint32_t kb = (uint32_t)(ks * 32);
            uint32_t ah[2][4], bh[4][4];
            ldsm4(pA + aoff + kb, ah[0]);
            ldsm4(pA + aoff + 16 * ASTR * 2 + kb, ah[1]);
#pragma unroll
            for (int pn = 0; pn < 4; pn++)
                ldsm4(pB + boff + pn * 16 * ASTR * 2 + kb, bh[pn]);
#pragma unroll
            for (int mi = 0; mi < 2; mi++) {
#pragma unroll
                for (int ni = 0; ni < 8; ni++) {
                    int pn = ni >> 1, o = ni & 1;
                    mma16816(acc[mi][ni], ah[mi], bh[pn][o], bh[pn][o + 2]);
                }
            }
        }
        if (chunk + 1 < NCHUNK) {
            storeB(1 - buf);
            cpasync_wait0();
            __syncthreads();
        }
    }

    // ---- epilogue: bias add + direct stores ----
    int batch = b0 + (w & 1);
#pragma unroll
    for (int mi = 0; mi < 2; mi++) {
#pragma unroll
        for (int rr = 0; rr < 2; rr++) {
            int r = mrow0 + mi * 16 + rr * 8 + (lane >> 2);
            int gr = mtile * 128 + r;
            bool ismain = (gr < CO_MAIN);
            float bias = ismain ? main_b[n * CO_MAIN + gr]
                                : proj_b[n * CO_PROJ + (gr - CO_MAIN)];
            float* dst = ismain
                ? g_gates + ((size_t)batch * CO_MAIN + gr) * PIX
                : g_kqv  + ((size_t)batch * CO_PROJ + (gr - CO_MAIN)) * PIX;
#pragma unroll
            for (int ni = 0; ni < 8; ni++) {
                int pxc = ni * 8 + (lane & 3) * 2;
                float2 v;
                v.x = acc[mi][ni][rr * 2 + 0] + bias;
                v.y = acc[mi][ni][rr * 2 + 1] + bias;
                *(float2*)&dst[pxc] = v;
            }
        }
    }
}

// ---------------- attention over rolling memory ----------------
__global__ void attn_kernel(const float* __restrict__ k0,
                            const float* __restrict__ v0,
                            const float* __restrict__ pos_w,
                            const float* __restrict__ pos_b,
                            int n) {
    int b = blockIdx.x;
    int h = blockIdx.y;
    int tid = threadIdx.x;
    __shared__ float q[THD], kn[THD], vn[THD];
    __shared__ float sc[MEM], wts[MEM];

    const float* kqv = g_kqv + (size_t)b * CO_PROJ * PIX;
    const float rscale = 0.044194173824159216f;  // 1/sqrt(512)
    for (int d = tid; d < THD; d += 256) {
        int hd = d >> 6, hw = d & 63;
        kn[d] = kqv[(h * 24 + hd) * PIX + hw];
        q[d]  = kqv[(h * 24 + 8 + hd) * PIX + hw] * rscale;
        vn[d] = kqv[(h * 24 + 16 + hd) * PIX + hw];
    }
    __syncthreads();

    const float* kb  = k0 + ((((size_t)n * BB + b) * NHH + h) * MEM) * THD;
    const float* pwb = pos_w + (size_t)n * MEM * (NHH * THD) + h * THD;
    int warp = tid >> 5, lane = tid & 31;
    for (int m = warp; m < MEM; m += 8) {
        const float* kr = (m < MEM - 1) ? (kb + (size_t)(m + 1) * THD) : kn;
        const float* pr = pwb + (size_t)m * (NHH * THD);
        float p = 0.0f;
        for (int d = lane; d < THD; d += 32)
            p = fmaf(q[d], kr[d] + pr[d], p);
#pragma unroll
        for (int o = 16; o; o >>= 1) p += __shfl_xor_sync(0xffffffffu, p, o);
        if (lane == 0)
            sc[m] = p + g_bias[b * MEM + m] + pos_b[(size_t)n * MEM * NHH + m * NHH + h];
    }
    __syncthreads();
    if (tid == 0) {
        float mx = sc[0];
#pragma unroll
        for (int m = 1; m < MEM; m++) mx = fmaxf(mx, sc[m]);
        float s = 0.0f;
#pragma unroll
        for (int m = 0; m < MEM; m++) {
            float e = __expf(sc[m] - mx);
            wts[m] = e;
            s += e;
        }
        float inv = 1.0f / s;
#pragma unroll
        for (int m = 0; m < MEM; m++) wts[m] *= inv;
    }
    __syncthreads();

    const float* vb = v0 + ((((size_t)n * BB + b) * NHH + h) * MEM) * THD;
    for (int d = tid; d < THD; d += 256) {
        float acc = wts[MEM - 1] * vn[d];
        for (int m = 0; m < MEM - 1; m++)
            acc = fmaf(wts[m], vb[(size_t)(m + 1) * THD + d], acc);
        int hd = d >> 6, hw = d & 63;
        g_attn[(size_t)b * (EE * PIX) + (h * 8 + hd) * PIX + hw] = acc;
    }
}

// ---------------- out conv + residual (parallel over 4 co-groups) --------
__global__ void __launch_bounds__(128, 8)
final_conv_kernel(const float* __restrict__ out_w,
                  const float* __restrict__ out_b,
                  const float* __restrict__ x,
                  int n) {
    __shared__ float sa[EE * 100];   // padded attn input
    int b = blockIdx.x;
    int g = blockIdx.y;              // co group: [g*16, g*16+16)
    int tid = threadIdx.x;           // 128

    for (int i = tid; i < EE * 100; i += 128) sa[i] = 0.0f;
    __syncthreads();
    const float* at = g_attn + (size_t)b * EE * PIX;
    for (int i = tid; i < EE * PIX; i += 128) {
        int c = i >> 6, p = i & 63;
        sa[c * 100 + ((p >> 3) + 1) * 10 + (p & 7) + 1] = at[i];
    }
    __syncthreads();

    int co = g * 16 + (tid >> 3);
    int row = tid & 7;
    const float* wc = out_w + ((size_t)n * EE + co) * EE * 9;
    float acc[8];
#pragma unroll
    for (int xx = 0; xx < 8; xx++) acc[xx] = 0.0f;
    for (int c = 0; c < EE; c++) {
        const float* s = sa + c * 100 + row * 10;
        const float* w = wc + c * 9;
        float w0 = w[0], w1 = w[1], w2 = w[2];
        float w3 = w[3], w4 = w[4], w5 = w[5];
        float w6 = w[6], w7 = w[7], w8 = w[8];
#pragma unroll
        for (int xx = 0; xx < 8; xx++) {
            float a = acc[xx];
            a = fmaf(s[xx],      w0, a);
            a = fmaf(s[xx + 1],  w1, a);
            a = fmaf(s[xx + 2],  w2, a);
            a = fmaf(s[10 + xx],     w3, a);
            a = fmaf(s[10 + xx + 1], w4, a);
            a = fmaf(s[10 + xx + 2], w5, a);
            a = fmaf(s[20 + xx],     w6, a);
            a = fmaf(s[20 + xx + 1], w7, a);
            a = fmaf(s[20 + xx + 2], w8, a);
            acc[xx] = a;
        }
    }
    float bb = out_b[n * EE + co];
    const float* xr = x + (size_t)b * EE * PIX;
    float* dst = g_ao + (size_t)b * EE * PIX + co * PIX + row * 8;
    int base = co * PIX + row * 8;
#pragma unroll
    for (int xx = 0; xx < 8; xx++)
        dst[xx] = acc[xx] + bb + xr[base + xx];
}

// ---------------- layernorm + LSTM combine ----------------
__global__ void final_ln_kernel(const float* __restrict__ ln_w,
                                const float* __restrict__ ln_b,
                                const float* __restrict__ c0,
                                int n, float* __restrict__ dst_last, int last) {
    __shared__ float red[16];
    __shared__ float s_mu, s_rv;
    int b = blockIdx.x;
    int tid = threadIdx.x;

    const float* aop = g_ao + (size_t)b * EE * PIX;
    float v16[16];
    float s1 = 0.0f, s2 = 0.0f;
#pragma unroll
    for (int j = 0; j < 16; j++) {
        float v = aop[tid + 256 * j];
        v16[j] = v;
        s1 += v;
        s2 += v * v;
    }
    int warp = tid >> 5, lane = tid & 31;
#pragma unroll
    for (int o = 16; o; o >>= 1) {
        s1 += __shfl_xor_sync(0xffffffffu, s1, o);
        s2 += __shfl_xor_sync(0xffffffffu, s2, o);
    }
    if (lane == 0) { red[warp] = s1; red[8 + warp] = s2; }
    __syncthreads();
    if (tid == 0) {
        float a = 0.0f, q2 = 0.0f;
#pragma unroll
        for (int w2 = 0; w2 < 8; w2++) { a += red[w2]; q2 += red[8 + w2]; }
        float mu = a * (1.0f / 4096.0f);
        float var = q2 * (1.0f / 4096.0f) - mu * mu;
        s_mu = mu;
        s_rv = rsqrtf(var + 1e-5f);
    }
    __syncthreads();
    float mu = s_mu, rv = s_rv;

    const float* gb = g_gates + (size_t)b * CO_MAIN * PIX;
    const float* cb = c0 + ((size_t)n * BB + b) * (EE * PIX);
    float nd = g_nd[b];
    float* dst = (last ? dst_last : g_out) + (size_t)b * EE * PIX;
    const float* lw = ln_w + (size_t)n * EE * PIX;
    const float* lb = ln_b + (size_t)n * EE * PIX;
#pragma unroll
    for (int j = 0; j < 16; j++) {
        int i = tid + 256 * j;
        int c = i >> 6, p = i & 63;
        float aon = (v16[j] - mu) * rv * lw[i] + lb[i];
        float gi = sigmoidf_(gb[(0 * EE + c) * PIX + p]);
        float gf = sigmoidf_(gb[(1 * EE + c) * PIX + p]);
        float go = sigmoidf_(gb[(2 * EE + c) * PIX + p]);
        float gg = tanhf(gb[(3 * EE + c) * PIX + p]);
        float ga = sigmoidf_(gb[(4 * EE + c) * PIX + p]);
        float cn = gf * (cb[i] * nd) + gi * gg + ga * tanhf(aon);
        dst[i] = go * tanhf(cn);
    }
}

// ---------------- launch ----------------
extern "C" void kernel_launch(void* const* d_in, const int* in_sizes, int n_in,
                              void* d_out, int out_size) {
    const float* x       = (const float*)d_in[0];
    const float* h0      = (const float*)d_in[1];
    const float* c0      = (const float*)d_in[2];
    const float* k0      = (const float*)d_in[3];
    const float* v0      = (const float*)d_in[4];
    const void*  src_mask = d_in[5];
    const void*  notdone  = d_in[6];
    const float* main_w  = (const float*)d_in[7];
    const float* main_b  = (const float*)d_in[8];
    const float* proj_w  = (const float*)d_in[9];
    const float* proj_b  = (const float*)d_in[10];
    const float* out_w   = (const float*)d_in[11];
    const float* out_b   = (const float*)d_in[12];
    const float* ln_w    = (const float*)d_in[13];
    const float* ln_b    = (const float*)d_in[14];
    const float* pos_w   = (const float*)d_in[15];
    const float* pos_b   = (const float*)d_in[16];
    float* out = (float*)d_out;

    cudaFuncSetAttribute(conv_mma_kernel,
                         cudaFuncAttributeMaxDynamicSharedMemorySize, MMA_SMEM);

    detect_kernel<<<1, 256>>>((const int*)src_mask);
    bias_kernel<<<(BB * MEM + 255) / 256, 256>>>(src_mask, notdone);
    wprep_kernel<<<2 * 4 * NCHUNK, 256>>>(main_w, proj_w);
    for (int n = 0; n < LNUM; n++) {
        int tot = BB * (C_MAIN / 2) * PIX;
        prep_kernel<<<(tot + 255) / 256, 256>>>(x, h0, n, n == 0 ? 1 : 0);
        conv_mma_kernel<<<dim3(64, 4), 256, MMA_SMEM>>>(main_b, proj_b, n);
        attn_kernel<<<dim3(BB, NHH), 256>>>(k0, v0, pos_w, pos_b, n);
        final_conv_kernel<<<dim3(BB, 4), 128>>>(out_w, out_b, x, n);
        final_ln_kernel<<<BB, 256>>>(ln_w, ln_b, c0, n,
                                     out, n == LNUM - 1 ? 1 : 0);
    }
}